// round 10
// baseline (speedup 1.0000x reference)
#include <cuda_runtime.h>
#include <cuda_bf16.h>
#include <math.h>
#include <stdint.h>

#define N_SEQ 512
#define LEN   128
#define LL2   256
#define DM    256
#define DT    32
#define DIN   288
#define KP    288
#define KE    384
#define ROWS  (N_SEQ*LEN)   // 65536
#define ROWS2 (N_SEQ*LL2)   // 131072

#define TILE_B   10240               // 128 rows * 80 bytes
#define SMEM_MMA (8 * TILE_B)        // 81920

// ---------------- scratch ----------------------------------------------------
__device__ float g_emb[ROWS*KE];
__device__ float g_cur[2][ROWS*DM];
__device__ __nv_bfloat16 g_cih[(size_t)ROWS2*KP];
__device__ __nv_bfloat16 g_cil[(size_t)ROWS2*KP];
__device__ __nv_bfloat16 g_temh[ROWS*DT];
__device__ __nv_bfloat16 g_teml[ROWS*DT];
__device__ __nv_bfloat16 g_wTh[3*4*256*KP];
__device__ __nv_bfloat16 g_wTl[3*4*256*KP];
__device__ __nv_bfloat16 g_qh[(size_t)ROWS2*DM];
__device__ __nv_bfloat16 g_ql[(size_t)ROWS2*DM];
__device__ __nv_bfloat16 g_kh[(size_t)ROWS2*DM];
__device__ __nv_bfloat16 g_kl[(size_t)ROWS2*DM];
__device__ float g_v[ROWS2*DM];
__device__ __nv_bfloat16 g_vTh[(size_t)N_SEQ*DM*LEN];
__device__ __nv_bfloat16 g_vTl[(size_t)N_SEQ*DM*LEN];
__device__ float g_p[N_SEQ*LL2*LEN];
__device__ __nv_bfloat16 g_ph[(size_t)N_SEQ*LL2*LEN];
__device__ __nv_bfloat16 g_pl[(size_t)N_SEQ*LL2*LEN];
__device__ float g_pd[N_SEQ*LL2];
__device__ float g_sv[N_SEQ*DM];
__device__ float g_o[ROWS2*DM];

// ---------------- helpers -----------------------------------------------------
__device__ __forceinline__ uint32_t smem_u32(const void* p) {
    uint32_t a;
    asm("{ .reg .u64 t; cvta.to.shared.u64 t, %1; cvt.u32.u64 %0, t; }" : "=r"(a) : "l"(p));
    return a;
}
#define LDSM4(r0, r1, r2, r3, addr) \
    asm volatile("ldmatrix.sync.aligned.m8n8.x4.shared.b16 {%0,%1,%2,%3}, [%4];" \
        : "=r"(r0), "=r"(r1), "=r"(r2), "=r"(r3) : "r"(addr))
#define MMA16816(c, a, b0, b1) \
    asm volatile("mma.sync.aligned.m16n8k16.row.col.f32.bf16.bf16.f32 " \
        "{%0,%1,%2,%3},{%4,%5,%6,%7},{%8,%9},{%0,%1,%2,%3};" \
        : "+f"((c)[0]), "+f"((c)[1]), "+f"((c)[2]), "+f"((c)[3]) \
        : "r"((a)[0]), "r"((a)[1]), "r"((a)[2]), "r"((a)[3]), "r"(b0), "r"(b1))
#define CPASYNC16(dst, src) \
    asm volatile("cp.async.ca.shared.global [%0], [%1], 16;" :: "r"(dst), "l"(src))
#define CPCOMMIT() asm volatile("cp.async.commit_group;" ::: "memory")
#define CPWAIT0()  asm volatile("cp.async.wait_group 0;" ::: "memory")
#define CPWAIT1()  asm volatile("cp.async.wait_group 1;" ::: "memory")

__device__ __forceinline__ void split_store(__nv_bfloat16* ph, __nv_bfloat16* pl,
                                            size_t idx, float v) {
    __nv_bfloat16 hi = __float2bfloat16(v);
    ph[idx] = hi;
    pl[idx] = __float2bfloat16(v - __bfloat162float(hi));
}

// ---------------- fused 3-term mma core ---------------------------------------
__device__ __forceinline__ void mma_core3(
    const __nv_bfloat16* Ah, const __nv_bfloat16* Al,
    const __nv_bfloat16* Bh, const __nv_bfloat16* Bl,
    int lda, int ldb, int nkt, uint32_t sbase, float acc[4][4][4])
{
    int tid = threadIdx.x;
    int w = tid >> 5, lane = tid & 31;
    int wm = (w & 1) << 6;
    int wn = (w >> 1) << 5;
    int lr = tid >> 1;
    int c2 = (tid & 1) << 1;

    const char* pAh = (const char*)(Ah + (size_t)lr * lda) + c2 * 16;
    const char* pAl = (const char*)(Al + (size_t)lr * lda) + c2 * 16;
    const char* pBh = (const char*)(Bh + (size_t)lr * ldb) + c2 * 16;
    const char* pBl = (const char*)(Bl + (size_t)lr * ldb) + c2 * 16;
    uint32_t sdst = sbase + lr * 80 + c2 * 16;

    {
        CPASYNC16(sdst,              pAh);       CPASYNC16(sdst + 16,              pAh + 16);
        CPASYNC16(sdst + TILE_B,     pAl);       CPASYNC16(sdst + TILE_B + 16,     pAl + 16);
        CPASYNC16(sdst + 2*TILE_B,   pBh);       CPASYNC16(sdst + 2*TILE_B + 16,   pBh + 16);
        CPASYNC16(sdst + 3*TILE_B,   pBl);       CPASYNC16(sdst + 3*TILE_B + 16,   pBl + 16);
        CPCOMMIT();
    }

    int buf = 0;
    for (int kt = 0; kt < nkt; kt++) {
        bool more = (kt + 1 < nkt);
        if (more) {
            int off = (kt + 1) * 64;
            uint32_t d = sdst + (buf ^ 1) * (4 * TILE_B);
            CPASYNC16(d,              pAh + off);       CPASYNC16(d + 16,              pAh + off + 16);
            CPASYNC16(d + TILE_B,     pAl + off);       CPASYNC16(d + TILE_B + 16,     pAl + off + 16);
            CPASYNC16(d + 2*TILE_B,   pBh + off);       CPASYNC16(d + 2*TILE_B + 16,   pBh + off + 16);
            CPASYNC16(d + 3*TILE_B,   pBl + off);       CPASYNC16(d + 3*TILE_B + 16,   pBl + off + 16);
            CPCOMMIT();
            CPWAIT1();
        } else {
            CPWAIT0();
        }
        __syncthreads();

        uint32_t bAh = sbase + buf * (4 * TILE_B);
        uint32_t bAl = bAh + TILE_B;
        uint32_t bBh = bAh + 2 * TILE_B;
        uint32_t bBl = bAh + 3 * TILE_B;
#pragma unroll
        for (int ks = 0; ks < 2; ks++) {
            uint32_t arow = (uint32_t)((lane & 15)) * 80 + (uint32_t)(ks * 2 + ((lane >> 4) & 1)) * 16;
            uint32_t brow = (uint32_t)((lane & 7) + ((lane >> 4) & 1) * 8) * 80
                          + (uint32_t)(ks * 2 + ((lane >> 3) & 1)) * 16;
            uint32_t bh[2][4], bl[2][4];
#pragma unroll
            for (int p = 0; p < 2; p++) {
                uint32_t ad = (uint32_t)(wn + p * 16) * 80 + brow;
                LDSM4(bh[p][0], bh[p][1], bh[p][2], bh[p][3], bBh + ad);
                LDSM4(bl[p][0], bl[p][1], bl[p][2], bl[p][3], bBl + ad);
            }
            uint32_t a[4][4];
#pragma unroll
            for (int mf = 0; mf < 4; mf++) {
                uint32_t ad = (uint32_t)(wm + mf * 16) * 80 + arow;
                LDSM4(a[mf][0], a[mf][1], a[mf][2], a[mf][3], bAh + ad);
            }
#pragma unroll
            for (int mf = 0; mf < 4; mf++)
#pragma unroll
                for (int nf = 0; nf < 4; nf++) {
                    MMA16816(acc[mf][nf], a[mf], bh[nf >> 1][(nf & 1) * 2], bh[nf >> 1][(nf & 1) * 2 + 1]);
                    MMA16816(acc[mf][nf], a[mf], bl[nf >> 1][(nf & 1) * 2], bl[nf >> 1][(nf & 1) * 2 + 1]);
                }
#pragma unroll
            for (int mf = 0; mf < 4; mf++) {
                uint32_t ad = (uint32_t)(wm + mf * 16) * 80 + arow;
                LDSM4(a[mf][0], a[mf][1], a[mf][2], a[mf][3], bAl + ad);
            }
#pragma unroll
            for (int mf = 0; mf < 4; mf++)
#pragma unroll
                for (int nf = 0; nf < 4; nf++)
                    MMA16816(acc[mf][nf], a[mf], bh[nf >> 1][(nf & 1) * 2], bh[nf >> 1][(nf & 1) * 2 + 1]);
        }
        __syncthreads();
        buf ^= 1;
    }
}

// ---------------- QKV epilogue -------------------------------------------------
__device__ __forceinline__ void qkv_epilogue(float acc[4][4][4], int z, int baseRow,
                                             int n0, const float* bias) {
    int w = threadIdx.x >> 5, lane = threadIdx.x & 31;
    int wm = (w & 1) << 6, wn = (w >> 1) << 5;
    int r0 = lane >> 2, c0 = (lane & 3) << 1;
#pragma unroll
    for (int mf = 0; mf < 4; mf++)
#pragma unroll
        for (int nf = 0; nf < 4; nf++) {
            int row = baseRow + wm + mf * 16 + r0;
            int col = n0 + wn + nf * 8 + c0;
#pragma unroll
            for (int q = 0; q < 4; q++) {
                size_t idx = (size_t)(row + (q >> 1) * 8) * DM + col + (q & 1);
                float val = acc[mf][nf][q] + bias[col + (q & 1)];
                if (z == 2) g_v[idx] = val;
                else if (z == 0) split_store(g_qh, g_ql, idx, val);
                else             split_store(g_kh, g_kl, idx, val);
            }
        }
}

// ---------------- fused prep ---------------------------------------------------
#define PR0 ((size_t)ROWS*KE)
#define PR1 (PR0 + (size_t)ROWS*16)
#define PR2 (PR1 + (size_t)2*ROWS*DM)
#define PR3 (PR2 + (size_t)3*4*256*KP)
__global__ void k_prep(const int* __restrict__ subj, const int* __restrict__ obj,
                       const int* __restrict__ rel, const float* __restrict__ ent,
                       const float* __restrict__ relw, const float* __restrict__ time,
                       const float* __restrict__ qw, const float* __restrict__ kw,
                       const float* __restrict__ vw) {
    size_t i = (size_t)blockIdx.x * 256 + threadIdx.x;
    if (i < PR0) {
        int row = (int)(i / KE);
        int c   = (int)(i - (size_t)row * KE);
        float v;
        if (c < 128)      v = ent[subj[row] * 128 + c];
        else if (c < 256) v = ent[obj[row] * 128 + (c - 128)];
        else              v = relw[rel[row] * 128 + (c - 256)];
        g_emb[i] = v;
    } else if (i < PR1) {
        size_t j = i - PR0;
        int row = (int)(j >> 4);
        int f   = (int)(j & 15);
        float t = time[row];
        float div = expf((float)(2 * f) * -0.28782313662425576f);
        float arg = t * div;
        float np  = (t > 0.f) ? 1.f : 0.f;
        float s = sinf(arg) * np;
        float c = cosf(arg) * np;
        int n = row >> 7, l = row & 127;
        size_t rT = ((size_t)n * LL2 + l) * KP + 256 + 2 * f;
        size_t rB = rT + (size_t)128 * KP;
        split_store(g_cih, g_cil, rT, s);
        split_store(g_cih, g_cil, rT + 1, c);
        split_store(g_cih, g_cil, rB, s);
        split_store(g_cih, g_cil, rB + 1, c);
        split_store(g_temh, g_teml, (size_t)row * DT + 2 * f, s);
        split_store(g_temh, g_teml, (size_t)row * DT + 2 * f + 1, c);
    } else if (i < PR2) {
        ((float*)g_cur)[i - PR1] = 0.f;
    } else if (i < PR3) {
        size_t j = i - PR2;
        int k  = (int)(j % KP);
        int n  = (int)((j / KP) & 255);
        int hl = (int)((j / (KP * 256)) & 3);
        int z  = (int)(j / ((size_t)KP * 256 * 4));
        const float* W = (z == 0) ? qw : (z == 1) ? kw : vw;
        float v = W[(hl * DIN + k) * 256 + n];
        split_store(g_wTh, g_wTl, j, v);
    }
}

// ---------------- QKV: full (l=1) ----------------------------------------------
__global__ __launch_bounds__(256, 2) void k_qkv_mma(const float* __restrict__ qb,
                                                    const float* __restrict__ kb,
                                                    const float* __restrict__ vb, int hl) {
    extern __shared__ __nv_bfloat16 smem_dyn[];
    uint32_t sbase = smem_u32(smem_dyn);
    int z  = blockIdx.x >> 1;
    int n0 = (blockIdx.x & 1) << 7;
    int m0 = blockIdx.y << 7;

    float acc[4][4][4] = {};
    mma_core3(g_cih + (size_t)m0 * KP, g_cil + (size_t)m0 * KP,
              g_wTh + ((size_t)(z * 4 + hl) * 256 + n0) * KP,
              g_wTl + ((size_t)(z * 4 + hl) * 256 + n0) * KP,
              KP, KP, 9, sbase, acc);
    qkv_epilogue(acc, z, m0, n0, ((z == 0) ? qb : (z == 1) ? kb : vb) + hl * 256);
}

// ---------------- QKV at l=0: fused top (K=288) + bottom (K=32) ----------------
__global__ __launch_bounds__(256, 2) void k_qkv_l0(const float* __restrict__ qb,
                                                   const float* __restrict__ kb,
                                                   const float* __restrict__ vb, int hl) {
    extern __shared__ __nv_bfloat16 smem_dyn[];
    uint32_t sbase = smem_u32(smem_dyn);
    int z  = blockIdx.x >> 1;
    int n0 = (blockIdx.x & 1) << 7;
    const float* bias = ((z == 0) ? qb : (z == 1) ? kb : vb) + hl * 256;

    float acc[4][4][4] = {};
    if (blockIdx.y < N_SEQ) {
        int m0 = blockIdx.y << 8;       // top half of seq blockIdx.y
        mma_core3(g_cih + (size_t)m0 * KP, g_cil + (size_t)m0 * KP,
                  g_wTh + ((size_t)(z * 4 + hl) * 256 + n0) * KP,
                  g_wTl + ((size_t)(z * 4 + hl) * 256 + n0) * KP,
                  KP, KP, 9, sbase, acc);
        qkv_epilogue(acc, z, m0, n0, bias);
    } else {
        int n = blockIdx.y - N_SEQ;     // bottom half, tem-only K=32
        mma_core3(g_temh + (size_t)n * 128 * DT, g_teml + (size_t)n * 128 * DT,
                  g_wTh + ((size_t)(z * 4 + hl) * 256 + n0) * KP + 256,
                  g_wTl + ((size_t)(z * 4 + hl) * 256 + n0) * KP + 256,
                  DT, KP, 1, sbase, acc);
        qkv_epilogue(acc, z, n * LL2 + 128, n0, bias);
    }
}

// ---------------- fused scores + V-transpose + sv ------------------------------
// grid (11, N_SEQ): x<2 scores m-blocks; x in [2,10) vt d-slices; x==10 sv.
__global__ __launch_bounds__(256, 2) void k_scores_vtsv() {
    extern __shared__ __nv_bfloat16 smem_dyn[];
    int n  = blockIdx.y;
    int xx = blockIdx.x;

    if (xx < 2) {
        uint32_t sbase = smem_u32(smem_dyn);
        int m0 = xx << 7;
        float acc[4][4][4] = {};
        mma_core3(g_qh + ((size_t)n * LL2 + m0) * DM, g_ql + ((size_t)n * LL2 + m0) * DM,
                  g_kh + (size_t)n * LL2 * DM, g_kl + (size_t)n * LL2 * DM,
                  DM, DM, 8, sbase, acc);
        int w = threadIdx.x >> 5, lane = threadIdx.x & 31;
        int wm = (w & 1) << 6, wn = (w >> 1) << 5;
        int r0 = lane >> 2, c0 = (lane & 3) << 1;
        float* P = g_p + ((size_t)n * LL2 + m0) * LEN;
#pragma unroll
        for (int mf = 0; mf < 4; mf++)
#pragma unroll
            for (int nf = 0; nf < 4; nf++) {
                int row = wm + mf * 16 + r0;
                int col = wn + nf * 8 + c0;
                P[(size_t)row * LEN + col]           = acc[mf][nf][0] * 0.0625f;
                P[(size_t)row * LEN + col + 1]       = acc[mf][nf][1] * 0.0625f;
                P[(size_t)(row + 8) * LEN + col]     = acc[mf][nf][2] * 0.0625f;
                P[(size_t)(row + 8) * LEN + col + 1] = acc[mf][nf][3] * 0.0625f;
            }
    } else if (xx < 10) {
        float (*tile)[33] = (float (*)[33])smem_dyn;
        int d0 = (xx - 2) << 5;
        for (int el = threadIdx.x; el < 4096; el += 256) {
            int key = el >> 5, d = el & 31;
            tile[key][d] = g_v[((size_t)n * LL2 + key) * DM + d0 + d];
        }
        __syncthreads();
        for (int el = threadIdx.x; el < 4096; el += 256) {
            int d = el >> 7, key = el & 127;
            size_t o = (size_t)n * DM * LEN + (size_t)(d0 + d) * LEN + key;
            split_store(g_vTh, g_vTl, o, tile[key][d]);
        }
    } else {
        int d = threadIdx.x;
        const float* vp = g_v + (n * LL2 + LEN) * DM + d;
        float s = 0.f;
#pragma unroll 8
        for (int j = 0; j < LEN; j++) s += vp[j * DM];
        g_sv[n * DM + d] = s;
    }
}

// ---------------- masked softmax -> bf16 hi/lo ---------------------------------
__global__ __launch_bounds__(256) void k_softmax(const float* __restrict__ time) {
    int warp = threadIdx.x >> 5, lane = threadIdx.x & 31;
    int rowId = blockIdx.x * 8 + warp;
    int n = rowId >> 8;
    int i = rowId & 255;
    const float* row = g_p + (size_t)rowId * LEN;
    __nv_bfloat16* oh = g_ph + (size_t)rowId * LEN;
    __nv_bfloat16* ol = g_pl + (size_t)rowId * LEN;
    const float* tt = time + n * LEN;
    bool bottom = (i >= LEN);
    int iq = bottom ? i - LEN : i;

    float vals[4];
    float mx = -1e30f;
#pragma unroll
    for (int c = 0; c < 4; c++) {
        int j = lane + c * 32;
        float s = row[j];
        bool masked = (j >= iq) || (tt[j] == 0.f);
        s = masked ? -1e9f : s;
        vals[c] = s;
        mx = fmaxf(mx, s);
    }
    float d = 0.f;
    if (bottom) {
        size_t base = (size_t)(n * LL2 + i) * DM / 2;
        const __nv_bfloat162* qh2 = (const __nv_bfloat162*)g_qh + base;
        const __nv_bfloat162* ql2 = (const __nv_bfloat162*)g_ql + base;
        const __nv_bfloat162* kh2 = (const __nv_bfloat162*)g_kh + base;
        const __nv_bfloat162* kl2 = (const __nv_bfloat162*)g_kl + base;
#pragma unroll
        for (int c = 0; c < 4; c++) {
            int idx = lane * 4 + c;
            __nv_bfloat162 a = qh2[idx], b = ql2[idx], e = kh2[idx], f = kl2[idx];
            float qx = __bfloat162float(a.x) + __bfloat162float(b.x);
            float qy = __bfloat162float(a.y) + __bfloat162float(b.y);
            float kx = __bfloat162float(e.x) + __bfloat162float(f.x);
            float ky = __bfloat162float(e.y) + __bfloat162float(f.y);
            d += qx * kx + qy * ky;
        }
#pragma unroll
        for (int off = 16; off; off >>= 1) d += __shfl_xor_sync(0xffffffffu, d, off);
        d *= 0.0625f;
    }
#pragma unroll
    for (int off = 16; off; off >>= 1) mx = fmaxf(mx, __shfl_xor_sync(0xffffffffu, mx, off));

    if (!bottom && mx < -5e8f) {
        __nv_bfloat16 u = __float2bfloat16(1.0f / 256.0f);
#pragma unroll
        for (int c = 0; c < 4; c++) { oh[lane + c * 32] = u; ol[lane + c * 32] = __float2bfloat16(0.f); }
        if (lane == 0) g_pd[rowId] = 1.0f / 256.0f;
        return;
    }
    if (bottom) mx = fmaxf(mx, d);
    float sum = 0.f;
#pragma unroll
    for (int c = 0; c < 4; c++) { vals[c] = expf(vals[c] - mx); sum += vals[c]; }
#pragma unroll
    for (int off = 16; off; off >>= 1) sum += __shfl_xor_sync(0xffffffffu, sum, off);
    float ed = bottom ? expf(d - mx) : 0.f;
    float inv = 1.f / (sum + ed);
#pragma unroll
    for (int c = 0; c < 4; c++) {
        float p = vals[c] * inv;
        __nv_bfloat16 hi = __float2bfloat16(p);
        oh[lane + c * 32] = hi;
        ol[lane + c * 32] = __float2bfloat16(p - __bfloat162float(hi));
    }
    if (lane == 0) g_pd[rowId] = ed * inv;
}

// ---------------- PV mma -------------------------------------------------------
__global__ __launch_bounds__(256, 2) void k_pv_mma() {
    extern __shared__ __nv_bfloat16 smem_dyn[];
    uint32_t sbase = smem_u32(smem_dyn);
    int n  = blockIdx.z;
    int m0 = blockIdx.y << 7;
    int n0 = blockIdx.x << 7;

    float acc[4][4][4] = {};
    mma_core3(g_ph + ((size_t)n * LL2 + m0) * LEN, g_pl + ((size_t)n * LL2 + m0) * LEN,
              g_vTh + ((size_t)n * DM + n0) * LEN, g_vTl + ((size_t)n * DM + n0) * LEN,
              LEN, LEN, 4, sbase, acc);

    int w = threadIdx.x >> 5, lane = threadIdx.x & 31;
    int wm = (w & 1) << 6, wn = (w >> 1) << 5;
    int r0 = lane >> 2, c0 = (lane & 3) << 1;
    const float* V = g_v + (size_t)n * LL2 * DM;
    float* O = g_o + (size_t)n * LL2 * DM;
#pragma unroll
    for (int mf = 0; mf < 4; mf++)
#pragma unroll
        for (int nf = 0; nf < 4; nf++) {
            int row = m0 + wm + mf * 16 + r0;
            int col = n0 + wn + nf * 8 + c0;
#pragma unroll
            for (int q = 0; q < 4; q++) {
                int r = row + (q >> 1) * 8;
                int c = col + (q & 1);
                float pd = g_pd[n * LL2 + r];
                float extra = (r < LEN) ? g_sv[n * DM + c] : V[(size_t)r * DM + c];
                O[(size_t)r * DM + c] = acc[mf][nf][q] + pd * extra;
            }
        }
}

// ---------------- fused residual update + next-iteration ci --------------------
__global__ void k_update_ci(const float* __restrict__ time, int h,
                            int writeTop, int writeBottom) {
    int i = blockIdx.x * 256 + threadIdx.x;
    if (i >= ROWS * DM) return;
    int row = i >> 8;
    int d   = i & 255;
    int n   = row >> 7;
    int l   = row & 127;
    float top = g_o[(n * LL2 + l) * DM + d];
    float bot = g_o[(n * LL2 + LEN + l) * DM + d];
    float np  = (time[row] > 0.f) ? 1.f : 0.f;
    float nc  = g_cur[h][i] + tanhf(bot * np);
    g_cur[h][i] = nc;
    if (writeTop)
        split_store(g_cih, g_cil, ((size_t)n * LL2 + l) * KP + d, top);
    if (writeBottom)
        split_store(g_cih, g_cil, ((size_t)n * LL2 + LEN + l) * KP + d, nc);
}

// ---------------- FFMA GEMM for input projection (writes ci) -------------------
__device__ __forceinline__ void gemm_compute(const float (*As)[140], const float (*Bs)[128],
                                             float acc[8][8], int tx, int ty) {
#pragma unroll
    for (int k = 0; k < 8; k++) {
        float a[8], b[8];
        *(float4*)(a)     = *(const float4*)&As[k][ty * 4];
        *(float4*)(a + 4) = *(const float4*)&As[k][64 + ty * 4];
        *(float4*)(b)     = *(const float4*)&Bs[k][tx * 4];
        *(float4*)(b + 4) = *(const float4*)&Bs[k][64 + tx * 4];
#pragma unroll
        for (int i = 0; i < 8; i++)
#pragma unroll
            for (int j = 0; j < 8; j++)
                acc[i][j] += a[i] * b[j];
    }
}

__global__ __launch_bounds__(256) void k_gemm_x(const float* __restrict__ W,
                                                const float* __restrict__ bias) {
    __shared__ float As[2][8][140];
    __shared__ float Bs[2][8][128];
    float acc[8][8] = {};
    int m0 = blockIdx.y << 7, n0 = blockIdx.x << 7;
    int tid = threadIdx.x;
    int tx = tid & 15, ty = tid >> 4;
    int ar = tid >> 1, kg = (tid & 1) << 2;
    int br = tid >> 5, bc = (tid & 31) << 2;

    float4 a = *(const float4*)(g_emb + (m0 + ar) * KE + kg);
    float4 b = *(const float4*)(W + br * DM + n0 + bc);
    As[0][kg][ar] = a.x; As[0][kg + 1][ar] = a.y; As[0][kg + 2][ar] = a.z; As[0][kg + 3][ar] = a.w;
    *(float4*)&Bs[0][br][bc] = b;
    __syncthreads();

    int buf = 0;
    for (int k0 = 8; k0 < KE; k0 += 8) {
        float4 an = *(const float4*)(g_emb + (m0 + ar) * KE + k0 + kg);
        float4 bn = *(const float4*)(W + (k0 + br) * DM + n0 + bc);
        gemm_compute(As[buf], Bs[buf], acc, tx, ty);
        int nb = buf ^ 1;
        As[nb][kg][ar] = an.x; As[nb][kg + 1][ar] = an.y; As[nb][kg + 2][ar] = an.z; As[nb][kg + 3][ar] = an.w;
        *(float4*)&Bs[nb][br][bc] = bn;
        __syncthreads();
        buf = nb;
    }
    gemm_compute(As[buf], Bs[buf], acc, tx, ty);

#pragma unroll
    for (int i = 0; i < 8; i++) {
        int r = m0 + ((i < 4) ? (ty << 2) + i : 64 + (ty << 2) + i - 4);
        int n = r >> 7, l = r & 127;
#pragma unroll
        for (int j = 0; j < 8; j++) {
            int c = n0 + ((j < 4) ? (tx << 2) + j : 64 + (tx << 2) + j - 4);
            split_store(g_cih, g_cil, ((size_t)n * LL2 + l) * KP + c, acc[i][j] + bias[c]);
        }
    }
}

// ---------------- final MLP head -----------------------------------------------
__global__ __launch_bounds__(256) void k_head(const float* __restrict__ w1,
                                              const float* __restrict__ b1,
                                              const float* __restrict__ w2,
                                              const float* __restrict__ b2,
                                              float* __restrict__ out) {
    int n = blockIdx.x;
    int t = threadIdx.x;
    __shared__ float sl[512];
    __shared__ float sh[256];
    sl[t]       = g_cur[0][(n * LEN + LEN - 1) * DM + t];
    sl[256 + t] = g_cur[1][(n * LEN + LEN - 1) * DM + t];
    __syncthreads();
    float acc = b1[t];
    for (int k = 0; k < 512; k++) acc += sl[k] * w1[k * DM + t];
    float x = acc;
    float g = 0.5f * x * (1.f + erff(x * 0.7071067811865476f));
    sh[t] = g * w2[t];
    __syncthreads();
    for (int s = 128; s > 0; s >>= 1) {
        if (t < s) sh[t] += sh[t + s];
        __syncthreads();
    }
    if (t == 0) out[n] = sh[0] + b2[0];
}

// ---------------- launch --------------------------------------------------------
extern "C" void kernel_launch(void* const* d_in, const int* in_sizes, int n_in,
                              void* d_out, int out_size) {
    const int*   subj = (const int*)d_in[0];
    const int*   obj  = (const int*)d_in[1];
    const int*   rel  = (const int*)d_in[2];
    const float* time = (const float*)d_in[3];
    const float* ent  = (const float*)d_in[4];
    const float* relw = (const float*)d_in[5];
    const float* in_w = (const float*)d_in[6];
    const float* in_b = (const float*)d_in[7];
    const float* q_w  = (const float*)d_in[8];
    const float* q_b  = (const float*)d_in[9];
    const float* k_w  = (const float*)d_in[10];
    const float* k_b  = (const float*)d_in[11];
    const float* v_w  = (const float*)d_in[12];
    const float* v_b  = (const float*)d_in[13];
    const float* w1   = (const float*)d_in[14];
    const float* b1   = (const float*)d_in[15];
    const float* w2   = (const float*)d_in[16];
    const float* b2   = (const float*)d_in[17];
    float* out = (float*)d_out;

    cudaFuncSetAttribute(k_qkv_mma,     cudaFuncAttributeMaxDynamicSharedMemorySize, SMEM_MMA);
    cudaFuncSetAttribute(k_qkv_l0,      cudaFuncAttributeMaxDynamicSharedMemorySize, SMEM_MMA);
    cudaFuncSetAttribute(k_scores_vtsv, cudaFuncAttributeMaxDynamicSharedMemorySize, SMEM_MMA);
    cudaFuncSetAttribute(k_pv_mma,      cudaFuncAttributeMaxDynamicSharedMemorySize, SMEM_MMA);

    k_prep<<<(unsigned)((PR3 + 255) / 256), 256>>>(subj, obj, rel, ent, relw, time, q_w, k_w, v_w);
    k_gemm_x<<<dim3(DM / 128, ROWS / 128), 256>>>(in_w, in_b);

    for (int h = 0; h < 2; h++) {
        for (int l = 0; l < 2; l++) {
            int hl = h * 2 + l;
            if (l == 0)
                k_qkv_l0<<<dim3(6, 2 * N_SEQ), 256, SMEM_MMA>>>(q_b, k_b, v_b, hl);
            else
                k_qkv_mma<<<dim3(6, ROWS2 / 128), 256, SMEM_MMA>>>(q_b, k_b, v_b, hl);
            k_scores_vtsv<<<dim3(11, N_SEQ), 256, SMEM_MMA>>>();
            k_softmax<<<(N_SEQ * LL2) / 8, 256>>>(time);
            k_pv_mma<<<dim3(2, 2, N_SEQ), 256, SMEM_MMA>>>();
            int it = h * 2 + l;
            k_update_ci<<<(ROWS * DM + 255) / 256, 256>>>(time, h, it < 3 ? 1 : 0, l == 0 ? 1 : 0);
        }
    }
    k_head<<<N_SEQ, 256>>>(w1, b1, w2, b2, out);
}

// round 14
// speedup vs baseline: 1.0519x; 1.0519x over previous
#include <cuda_runtime.h>
#include <cuda_bf16.h>
#include <math.h>
#include <stdint.h>

#define N_SEQ 512
#define LEN   128
#define LL2   256
#define DM    256
#define DT    32
#define DIN   288
#define KP    288
#define KE    384
#define ROWS  (N_SEQ*LEN)   // 65536
#define ROWS2 (N_SEQ*LL2)   // 131072

#define TILE_B   10240               // 128 rows * 80 bytes
#define SMEM_MMA (8 * TILE_B)        // 81920

// ---------------- scratch ----------------------------------------------------
__device__ float g_emb[ROWS*KE];
__device__ float g_cur[2][ROWS*DM];
__device__ __nv_bfloat16 g_cih[(size_t)ROWS2*KP];
__device__ __nv_bfloat16 g_cil[(size_t)ROWS2*KP];
__device__ __nv_bfloat16 g_temh[ROWS*DT];
__device__ __nv_bfloat16 g_teml[ROWS*DT];
__device__ __nv_bfloat16 g_wTh[3*4*256*KP];
__device__ __nv_bfloat16 g_wTl[3*4*256*KP];
__device__ __nv_bfloat16 g_qh[(size_t)ROWS2*DM];
__device__ __nv_bfloat16 g_ql[(size_t)ROWS2*DM];
__device__ __nv_bfloat16 g_kh[(size_t)ROWS2*DM];
__device__ __nv_bfloat16 g_kl[(size_t)ROWS2*DM];
__device__ float g_v[ROWS2*DM];
__device__ __nv_bfloat16 g_vTh[(size_t)N_SEQ*DM*LEN];
__device__ __nv_bfloat16 g_vTl[(size_t)N_SEQ*DM*LEN];
__device__ __nv_bfloat16 g_ph[(size_t)N_SEQ*LL2*LEN];
__device__ __nv_bfloat16 g_pl[(size_t)N_SEQ*LL2*LEN];
__device__ float g_pd[N_SEQ*LL2];
__device__ float g_sv[N_SEQ*DM];
__device__ float g_o[ROWS2*DM];

// ---------------- helpers -----------------------------------------------------
__device__ __forceinline__ uint32_t smem_u32(const void* p) {
    uint32_t a;
    asm("{ .reg .u64 t; cvta.to.shared.u64 t, %1; cvt.u32.u64 %0, t; }" : "=r"(a) : "l"(p));
    return a;
}
#define LDSM4(r0, r1, r2, r3, addr) \
    asm volatile("ldmatrix.sync.aligned.m8n8.x4.shared.b16 {%0,%1,%2,%3}, [%4];" \
        : "=r"(r0), "=r"(r1), "=r"(r2), "=r"(r3) : "r"(addr))
#define MMA16816(c, a, b0, b1) \
    asm volatile("mma.sync.aligned.m16n8k16.row.col.f32.bf16.bf16.f32 " \
        "{%0,%1,%2,%3},{%4,%5,%6,%7},{%8,%9},{%0,%1,%2,%3};" \
        : "+f"((c)[0]), "+f"((c)[1]), "+f"((c)[2]), "+f"((c)[3]) \
        : "r"((a)[0]), "r"((a)[1]), "r"((a)[2]), "r"((a)[3]), "r"(b0), "r"(b1))
#define CPASYNC16(dst, src) \
    asm volatile("cp.async.ca.shared.global [%0], [%1], 16;" :: "r"(dst), "l"(src))
#define CPCOMMIT() asm volatile("cp.async.commit_group;" ::: "memory")
#define CPWAIT0()  asm volatile("cp.async.wait_group 0;" ::: "memory")
#define CPWAIT1()  asm volatile("cp.async.wait_group 1;" ::: "memory")

__device__ __forceinline__ void split_store(__nv_bfloat16* ph, __nv_bfloat16* pl,
                                            size_t idx, float v) {
    __nv_bfloat16 hi = __float2bfloat16(v);
    ph[idx] = hi;
    pl[idx] = __float2bfloat16(v - __bfloat162float(hi));
}

// ---------------- fused 3-term mma core ---------------------------------------
__device__ __forceinline__ void mma_core3(
    const __nv_bfloat16* Ah, const __nv_bfloat16* Al,
    const __nv_bfloat16* Bh, const __nv_bfloat16* Bl,
    int lda, int ldb, int nkt, uint32_t sbase, float acc[4][4][4])
{
    int tid = threadIdx.x;
    int w = tid >> 5, lane = tid & 31;
    int wm = (w & 1) << 6;
    int wn = (w >> 1) << 5;
    int lr = tid >> 1;
    int c2 = (tid & 1) << 1;

    const char* pAh = (const char*)(Ah + (size_t)lr * lda) + c2 * 16;
    const char* pAl = (const char*)(Al + (size_t)lr * lda) + c2 * 16;
    const char* pBh = (const char*)(Bh + (size_t)lr * ldb) + c2 * 16;
    const char* pBl = (const char*)(Bl + (size_t)lr * ldb) + c2 * 16;
    uint32_t sdst = sbase + lr * 80 + c2 * 16;

    {
        CPASYNC16(sdst,              pAh);       CPASYNC16(sdst + 16,              pAh + 16);
        CPASYNC16(sdst + TILE_B,     pAl);       CPASYNC16(sdst + TILE_B + 16,     pAl + 16);
        CPASYNC16(sdst + 2*TILE_B,   pBh);       CPASYNC16(sdst + 2*TILE_B + 16,   pBh + 16);
        CPASYNC16(sdst + 3*TILE_B,   pBl);       CPASYNC16(sdst + 3*TILE_B + 16,   pBl + 16);
        CPCOMMIT();
    }

    int buf = 0;
    for (int kt = 0; kt < nkt; kt++) {
        bool more = (kt + 1 < nkt);
        if (more) {
            int off = (kt + 1) * 64;
            uint32_t d = sdst + (buf ^ 1) * (4 * TILE_B);
            CPASYNC16(d,              pAh + off);       CPASYNC16(d + 16,              pAh + off + 16);
            CPASYNC16(d + TILE_B,     pAl + off);       CPASYNC16(d + TILE_B + 16,     pAl + off + 16);
            CPASYNC16(d + 2*TILE_B,   pBh + off);       CPASYNC16(d + 2*TILE_B + 16,   pBh + off + 16);
            CPASYNC16(d + 3*TILE_B,   pBl + off);       CPASYNC16(d + 3*TILE_B + 16,   pBl + off + 16);
            CPCOMMIT();
            CPWAIT1();
        } else {
            CPWAIT0();
        }
        __syncthreads();

        uint32_t bAh = sbase + buf * (4 * TILE_B);
        uint32_t bAl = bAh + TILE_B;
        uint32_t bBh = bAh + 2 * TILE_B;
        uint32_t bBl = bAh + 3 * TILE_B;
#pragma unroll
        for (int ks = 0; ks < 2; ks++) {
            uint32_t arow = (uint32_t)((lane & 15)) * 80 + (uint32_t)(ks * 2 + ((lane >> 4) & 1)) * 16;
            uint32_t brow = (uint32_t)((lane & 7) + ((lane >> 4) & 1) * 8) * 80
                          + (uint32_t)(ks * 2 + ((lane >> 3) & 1)) * 16;
            uint32_t bh[2][4], bl[2][4];
#pragma unroll
            for (int p = 0; p < 2; p++) {
                uint32_t ad = (uint32_t)(wn + p * 16) * 80 + brow;
                LDSM4(bh[p][0], bh[p][1], bh[p][2], bh[p][3], bBh + ad);
                LDSM4(bl[p][0], bl[p][1], bl[p][2], bl[p][3], bBl + ad);
            }
            uint32_t a[4][4];
#pragma unroll
            for (int mf = 0; mf < 4; mf++) {
                uint32_t ad = (uint32_t)(wm + mf * 16) * 80 + arow;
                LDSM4(a[mf][0], a[mf][1], a[mf][2], a[mf][3], bAh + ad);
            }
#pragma unroll
            for (int mf = 0; mf < 4; mf++)
#pragma unroll
                for (int nf = 0; nf < 4; nf++) {
                    MMA16816(acc[mf][nf], a[mf], bh[nf >> 1][(nf & 1) * 2], bh[nf >> 1][(nf & 1) * 2 + 1]);
                    MMA16816(acc[mf][nf], a[mf], bl[nf >> 1][(nf & 1) * 2], bl[nf >> 1][(nf & 1) * 2 + 1]);
                }
#pragma unroll
            for (int mf = 0; mf < 4; mf++) {
                uint32_t ad = (uint32_t)(wm + mf * 16) * 80 + arow;
                LDSM4(a[mf][0], a[mf][1], a[mf][2], a[mf][3], bAl + ad);
            }
#pragma unroll
            for (int mf = 0; mf < 4; mf++)
#pragma unroll
                for (int nf = 0; nf < 4; nf++)
                    MMA16816(acc[mf][nf], a[mf], bh[nf >> 1][(nf & 1) * 2], bh[nf >> 1][(nf & 1) * 2 + 1]);
        }
        __syncthreads();
        buf ^= 1;
    }
}

// ---------------- QKV epilogue -------------------------------------------------
__device__ __forceinline__ void qkv_epilogue(float acc[4][4][4], int z, int baseRow,
                                             int n0, const float* bias) {
    int w = threadIdx.x >> 5, lane = threadIdx.x & 31;
    int wm = (w & 1) << 6, wn = (w >> 1) << 5;
    int r0 = lane >> 2, c0 = (lane & 3) << 1;
#pragma unroll
    for (int mf = 0; mf < 4; mf++)
#pragma unroll
        for (int nf = 0; nf < 4; nf++) {
            int row = baseRow + wm + mf * 16 + r0;
            int col = n0 + wn + nf * 8 + c0;
#pragma unroll
            for (int q = 0; q < 4; q++) {
                size_t idx = (size_t)(row + (q >> 1) * 8) * DM + col + (q & 1);
                float val = acc[mf][nf][q] + bias[col + (q & 1)];
                if (z == 2) g_v[idx] = val;
                else if (z == 0) split_store(g_qh, g_ql, idx, val);
                else             split_store(g_kh, g_kl, idx, val);
            }
        }
}

// ---------------- fused prep ---------------------------------------------------
#define PR0 ((size_t)ROWS*KE)
#define PR1 (PR0 + (size_t)ROWS*16)
#define PR2 (PR1 + (size_t)2*ROWS*DM)
#define PR3 (PR2 + (size_t)3*4*256*KP)
__global__ void k_prep(const int* __restrict__ subj, const int* __restrict__ obj,
                       const int* __restrict__ rel, const float* __restrict__ ent,
                       const float* __restrict__ relw, const float* __restrict__ time,
                       const float* __restrict__ qw, const float* __restrict__ kw,
                       const float* __restrict__ vw) {
    size_t i = (size_t)blockIdx.x * 256 + threadIdx.x;
    if (i < PR0) {
        int row = (int)(i / KE);
        int c   = (int)(i - (size_t)row * KE);
        float v;
        if (c < 128)      v = ent[subj[row] * 128 + c];
        else if (c < 256) v = ent[obj[row] * 128 + (c - 128)];
        else              v = relw[rel[row] * 128 + (c - 256)];
        g_emb[i] = v;
    } else if (i < PR1) {
        size_t j = i - PR0;
        int row = (int)(j >> 4);
        int f   = (int)(j & 15);
        float t = time[row];
        float div = expf((float)(2 * f) * -0.28782313662425576f);
        float arg = t * div;
        float np  = (t > 0.f) ? 1.f : 0.f;
        float s = sinf(arg) * np;
        float c = cosf(arg) * np;
        int n = row >> 7, l = row & 127;
        size_t rT = ((size_t)n * LL2 + l) * KP + 256 + 2 * f;
        size_t rB = rT + (size_t)128 * KP;
        split_store(g_cih, g_cil, rT, s);
        split_store(g_cih, g_cil, rT + 1, c);
        split_store(g_cih, g_cil, rB, s);
        split_store(g_cih, g_cil, rB + 1, c);
        split_store(g_temh, g_teml, (size_t)row * DT + 2 * f, s);
        split_store(g_temh, g_teml, (size_t)row * DT + 2 * f + 1, c);
    } else if (i < PR2) {
        ((float*)g_cur)[i - PR1] = 0.f;
    } else if (i < PR3) {
        size_t j = i - PR2;
        int k  = (int)(j % KP);
        int n  = (int)((j / KP) & 255);
        int hl = (int)((j / (KP * 256)) & 3);
        int z  = (int)(j / ((size_t)KP * 256 * 4));
        const float* W = (z == 0) ? qw : (z == 1) ? kw : vw;
        float v = W[(hl * DIN + k) * 256 + n];
        split_store(g_wTh, g_wTl, j, v);
    }
}

// ---------------- QKV mma (full / top-only) ------------------------------------
__global__ __launch_bounds__(256, 2) void k_qkv_mma(const float* __restrict__ qb,
                                                    const float* __restrict__ kb,
                                                    const float* __restrict__ vb,
                                                    int hl, int topOnly) {
    extern __shared__ __nv_bfloat16 smem_dyn[];
    uint32_t sbase = smem_u32(smem_dyn);
    int z  = blockIdx.x >> 1;
    int n0 = (blockIdx.x & 1) << 7;
    int m0 = topOnly ? (blockIdx.y << 8) : (blockIdx.y << 7);

    float acc[4][4][4] = {};
    mma_core3(g_cih + (size_t)m0 * KP, g_cil + (size_t)m0 * KP,
              g_wTh + ((size_t)(z * 4 + hl) * 256 + n0) * KP,
              g_wTl + ((size_t)(z * 4 + hl) * 256 + n0) * KP,
              KP, KP, 9, sbase, acc);
    qkv_epilogue(acc, z, m0, n0, ((z == 0) ? qb : (z == 1) ? kb : vb) + hl * 256);
}

// ---------------- QKV bottom fast path at l=0: K=32 (tem only) -----------------
__global__ __launch_bounds__(256, 2) void k_qkv_bot(const float* __restrict__ qb,
                                                    const float* __restrict__ kb,
                                                    const float* __restrict__ vb, int hl) {
    extern __shared__ __nv_bfloat16 smem_dyn[];
    uint32_t sbase = smem_u32(smem_dyn);
    int z  = blockIdx.x >> 1;
    int n0 = (blockIdx.x & 1) << 7;
    int n  = blockIdx.y;

    float acc[4][4][4] = {};
    mma_core3(g_temh + (size_t)n * 128 * DT, g_teml + (size_t)n * 128 * DT,
              g_wTh + ((size_t)(z * 4 + hl) * 256 + n0) * KP + 256,
              g_wTl + ((size_t)(z * 4 + hl) * 256 + n0) * KP + 256,
              DT, KP, 1, sbase, acc);
    qkv_epilogue(acc, z, n * LL2 + 128, n0, ((z == 0) ? qb : (z == 1) ? kb : vb) + hl * 256);
}

// ---------------- V transpose + sv ---------------------------------------------
__global__ __launch_bounds__(256) void k_vt() {
    __shared__ float tile[128][33];
    int n = blockIdx.y, d0 = blockIdx.x << 5;
    for (int el = threadIdx.x; el < 4096; el += 256) {
        int key = el >> 5, d = el & 31;
        tile[key][d] = g_v[((size_t)n * LL2 + key) * DM + d0 + d];
    }
    __syncthreads();
    for (int el = threadIdx.x; el < 4096; el += 256) {
        int d = el >> 7, key = el & 127;
        size_t o = (size_t)n * DM * LEN + (size_t)(d0 + d) * LEN + key;
        split_store(g_vTh, g_vTl, o, tile[key][d]);
    }
}

__global__ void k_sv() {
    int n = blockIdx.x;
    int d = threadIdx.x;
    const float* vp = g_v + (n * LL2 + LEN) * DM + d;
    float s = 0.f;
#pragma unroll 8
    for (int j = 0; j < LEN; j++) s += vp[j * DM];
    g_sv[n * DM + d] = s;
}

// ---------------- fused scores mma + masked softmax ----------------------------
// grid (2, N_SEQ): x = m-block. Scores tile kept in smem; softmax in-kernel.
__global__ __launch_bounds__(256, 2) void k_scores_sm(const float* __restrict__ time) {
    extern __shared__ __nv_bfloat16 smem_dyn[];
    uint32_t sbase = smem_u32(smem_dyn);
    int n  = blockIdx.y;
    int m0 = blockIdx.x << 7;

    float acc[4][4][4] = {};
    mma_core3(g_qh + ((size_t)n * LL2 + m0) * DM, g_ql + ((size_t)n * LL2 + m0) * DM,
              g_kh + (size_t)n * LL2 * DM, g_kl + (size_t)n * LL2 * DM,
              DM, DM, 8, sbase, acc);

    // spill scores to smem: P[128][132] fp32, then tt[128] after it
    float* P = (float*)smem_dyn;
    const int LDP = 132;
    float* stt = P + 128 * LDP;
    int w = threadIdx.x >> 5, lane = threadIdx.x & 31;
    int wm = (w & 1) << 6, wn = (w >> 1) << 5;
    int r0 = lane >> 2, c0 = (lane & 3) << 1;
#pragma unroll
    for (int mf = 0; mf < 4; mf++)
#pragma unroll
        for (int nf = 0; nf < 4; nf++) {
            int row = wm + mf * 16 + r0;
            int col = wn + nf * 8 + c0;
            P[row * LDP + col]           = acc[mf][nf][0] * 0.0625f;
            P[row * LDP + col + 1]       = acc[mf][nf][1] * 0.0625f;
            P[(row + 8) * LDP + col]     = acc[mf][nf][2] * 0.0625f;
            P[(row + 8) * LDP + col + 1] = acc[mf][nf][3] * 0.0625f;
        }
    if (threadIdx.x < 128) stt[threadIdx.x] = time[n * LEN + threadIdx.x];
    __syncthreads();

    bool bottom = (m0 == LEN);
    // warp-per-row softmax: warp w handles rows w*16 .. w*16+15
    for (int rr = 0; rr < 16; rr++) {
        int r = w * 16 + rr;                 // 0..127 within tile; iq = r
        int rowId = n * LL2 + m0 + r;
        __nv_bfloat16* oh = g_ph + (size_t)rowId * LEN;
        __nv_bfloat16* ol = g_pl + (size_t)rowId * LEN;

        float vals[4];
        float mx = -1e30f;
#pragma unroll
        for (int c = 0; c < 4; c++) {
            int j = lane + c * 32;
            float s = P[r * LDP + j];
            bool masked = (j >= r) || (stt[j] == 0.f);
            s = masked ? -1e9f : s;
            vals[c] = s;
            mx = fmaxf(mx, s);
        }
        float d = 0.f;
        if (bottom) {
            size_t base = (size_t)(n * LL2 + LEN + r) * DM / 2;
            const __nv_bfloat162* qh2 = (const __nv_bfloat162*)g_qh + base;
            const __nv_bfloat162* ql2 = (const __nv_bfloat162*)g_ql + base;
            const __nv_bfloat162* kh2 = (const __nv_bfloat162*)g_kh + base;
            const __nv_bfloat162* kl2 = (const __nv_bfloat162*)g_kl + base;
#pragma unroll
            for (int c = 0; c < 4; c++) {
                int idx = lane * 4 + c;
                __nv_bfloat162 a = qh2[idx], b = ql2[idx], e = kh2[idx], f = kl2[idx];
                float qx = __bfloat162float(a.x) + __bfloat162float(b.x);
                float qy = __bfloat162float(a.y) + __bfloat162float(b.y);
                float kx = __bfloat162float(e.x) + __bfloat162float(f.x);
                float ky = __bfloat162float(e.y) + __bfloat162float(f.y);
                d += qx * kx + qy * ky;
            }
#pragma unroll
            for (int off = 16; off; off >>= 1) d += __shfl_xor_sync(0xffffffffu, d, off);
            d *= 0.0625f;
        }
#pragma unroll
        for (int off = 16; off; off >>= 1) mx = fmaxf(mx, __shfl_xor_sync(0xffffffffu, mx, off));

        if (!bottom && mx < -5e8f) {
            __nv_bfloat16 u = __float2bfloat16(1.0f / 256.0f);
#pragma unroll
            for (int c = 0; c < 4; c++) { oh[lane + c * 32] = u; ol[lane + c * 32] = __float2bfloat16(0.f); }
            if (lane == 0) g_pd[rowId] = 1.0f / 256.0f;
            continue;
        }
        if (bottom) mx = fmaxf(mx, d);
        float sum = 0.f;
#pragma unroll
        for (int c = 0; c < 4; c++) { vals[c] = expf(vals[c] - mx); sum += vals[c]; }
#pragma unroll
        for (int off = 16; off; off >>= 1) sum += __shfl_xor_sync(0xffffffffu, sum, off);
        float ed = bottom ? expf(d - mx) : 0.f;
        float inv = 1.f / (sum + ed);
#pragma unroll
        for (int c = 0; c < 4; c++) {
            float p = vals[c] * inv;
            __nv_bfloat16 hi = __float2bfloat16(p);
            oh[lane + c * 32] = hi;
            ol[lane + c * 32] = __float2bfloat16(p - __bfloat162float(hi));
        }
        if (lane == 0) g_pd[rowId] = ed * inv;
    }
}

// ---------------- PV mma -------------------------------------------------------
__global__ __launch_bounds__(256, 2) void k_pv_mma() {
    extern __shared__ __nv_bfloat16 smem_dyn[];
    uint32_t sbase = smem_u32(smem_dyn);
    int n  = blockIdx.z;
    int m0 = blockIdx.y << 7;
    int n0 = blockIdx.x << 7;

    float acc[4][4][4] = {};
    mma_core3(g_ph + ((size_t)n * LL2 + m0) * LEN, g_pl + ((size_t)n * LL2 + m0) * LEN,
              g_vTh + ((size_t)n * DM + n0) * LEN, g_vTl + ((size_t)n * DM + n0) * LEN,
              LEN, LEN, 4, sbase, acc);

    int w = threadIdx.x >> 5, lane = threadIdx.x & 31;
    int wm = (w & 1) << 6, wn = (w >> 1) << 5;
    int r0 = lane >> 2, c0 = (lane & 3) << 1;
    const float* V = g_v + (size_t)n * LL2 * DM;
    float* O = g_o + (size_t)n * LL2 * DM;
#pragma unroll
    for (int mf = 0; mf < 4; mf++)
#pragma unroll
        for (int nf = 0; nf < 4; nf++) {
            int row = m0 + wm + mf * 16 + r0;
            int col = n0 + wn + nf * 8 + c0;
#pragma unroll
            for (int q = 0; q < 4; q++) {
                int r = row + (q >> 1) * 8;
                int c = col + (q & 1);
                float pd = g_pd[n * LL2 + r];
                float extra = (r < LEN) ? g_sv[n * DM + c] : V[(size_t)r * DM + c];
                O[(size_t)r * DM + c] = acc[mf][nf][q] + pd * extra;
            }
        }
}

// ---------------- fused residual update + next-iteration ci --------------------
__global__ void k_update_ci(const float* __restrict__ time, int h,
                            int writeTop, int writeBottom) {
    int i = blockIdx.x * 256 + threadIdx.x;
    if (i >= ROWS * DM) return;
    int row = i >> 8;
    int d   = i & 255;
    int n   = row >> 7;
    int l   = row & 127;
    float top = g_o[(n * LL2 + l) * DM + d];
    float bot = g_o[(n * LL2 + LEN + l) * DM + d];
    float np  = (time[row] > 0.f) ? 1.f : 0.f;
    float nc  = g_cur[h][i] + tanhf(bot * np);
    g_cur[h][i] = nc;
    if (writeTop)
        split_store(g_cih, g_cil, ((size_t)n * LL2 + l) * KP + d, top);
    if (writeBottom)
        split_store(g_cih, g_cil, ((size_t)n * LL2 + LEN + l) * KP + d, nc);
}

// ---------------- FFMA GEMM for input projection (writes ci) -------------------
__device__ __forceinline__ void gemm_compute(const float (*As)[140], const float (*Bs)[128],
                                             float acc[8][8], int tx, int ty) {
#pragma unroll
    for (int k = 0; k < 8; k++) {
        float a[8], b[8];
        *(float4*)(a)     = *(const float4*)&As[k][ty * 4];
        *(float4*)(a + 4) = *(const float4*)&As[k][64 + ty * 4];
        *(float4*)(b)     = *(const float4*)&Bs[k][tx * 4];
        *(float4*)(b + 4) = *(const float4*)&Bs[k][64 + tx * 4];
#pragma unroll
        for (int i = 0; i < 8; i++)
#pragma unroll
            for (int j = 0; j < 8; j++)
                acc[i][j] += a[i] * b[j];
    }
}

__global__ __launch_bounds__(256) void k_gemm_x(const float* __restrict__ W,
                                                const float* __restrict__ bias) {
    __shared__ float As[2][8][140];
    __shared__ float Bs[2][8][128];
    float acc[8][8] = {};
    int m0 = blockIdx.y << 7, n0 = blockIdx.x << 7;
    int tid = threadIdx.x;
    int tx = tid & 15, ty = tid >> 4;
    int ar = tid >> 1, kg = (tid & 1) << 2;
    int br = tid >> 5, bc = (tid & 31) << 2;

    float4 a = *(const float4*)(g_emb + (m0 + ar) * KE + kg);
    float4 b = *(const float4*)(W + br * DM + n0 + bc);
    As[0][kg][ar] = a.x; As[0][kg + 1][ar] = a.y; As[0][kg + 2][ar] = a.z; As[0][kg + 3][ar] = a.w;
    *(float4*)&Bs[0][br][bc] = b;
    __syncthreads();

    int buf = 0;
    for (int k0 = 8; k0 < KE; k0 += 8) {
        float4 an = *(const float4*)(g_emb + (m0 + ar) * KE + k0 + kg);
        float4 bn = *(const float4*)(W + (k0 + br) * DM + n0 + bc);
        gemm_compute(As[buf], Bs[buf], acc, tx, ty);
        int nb = buf ^ 1;
        As[nb][kg][ar] = an.x; As[nb][kg + 1][ar] = an.y; As[nb][kg + 2][ar] = an.z; As[nb][kg + 3][ar] = an.w;
        *(float4*)&Bs[nb][br][bc] = bn;
        __syncthreads();
        buf = nb;
    }
    gemm_compute(As[buf], Bs[buf], acc, tx, ty);

#pragma unroll
    for (int i = 0; i < 8; i++) {
        int r = m0 + ((i < 4) ? (ty << 2) + i : 64 + (ty << 2) + i - 4);
        int n = r >> 7, l = r & 127;
#pragma unroll
        for (int j = 0; j < 8; j++) {
            int c = n0 + ((j < 4) ? (tx << 2) + j : 64 + (tx << 2) + j - 4);
            split_store(g_cih, g_cil, ((size_t)n * LL2 + l) * KP + c, acc[i][j] + bias[c]);
        }
    }
}

// ---------------- final MLP head -----------------------------------------------
__global__ __launch_bounds__(256) void k_head(const float* __restrict__ w1,
                                              const float* __restrict__ b1,
                                              const float* __restrict__ w2,
                                              const float* __restrict__ b2,
                                              float* __restrict__ out) {
    int n = blockIdx.x;
    int t = threadIdx.x;
    __shared__ float sl[512];
    __shared__ float sh[256];
    sl[t]       = g_cur[0][(n * LEN + LEN - 1) * DM + t];
    sl[256 + t] = g_cur[1][(n * LEN + LEN - 1) * DM + t];
    __syncthreads();
    float acc = b1[t];
    for (int k = 0; k < 512; k++) acc += sl[k] * w1[k * DM + t];
    float x = acc;
    float g = 0.5f * x * (1.f + erff(x * 0.7071067811865476f));
    sh[t] = g * w2[t];
    __syncthreads();
    for (int s = 128; s > 0; s >>= 1) {
        if (t < s) sh[t] += sh[t + s];
        __syncthreads();
    }
    if (t == 0) out[n] = sh[0] + b2[0];
}

// ---------------- launch --------------------------------------------------------
extern "C" void kernel_launch(void* const* d_in, const int* in_sizes, int n_in,
                              void* d_out, int out_size) {
    const int*   subj = (const int*)d_in[0];
    const int*   obj  = (const int*)d_in[1];
    const int*   rel  = (const int*)d_in[2];
    const float* time = (const float*)d_in[3];
    const float* ent  = (const float*)d_in[4];
    const float* relw = (const float*)d_in[5];
    const float* in_w = (const float*)d_in[6];
    const float* in_b = (const float*)d_in[7];
    const float* q_w  = (const float*)d_in[8];
    const float* q_b  = (const float*)d_in[9];
    const float* k_w  = (const float*)d_in[10];
    const float* k_b  = (const float*)d_in[11];
    const float* v_w  = (const float*)d_in[12];
    const float* v_b  = (const float*)d_in[13];
    const float* w1   = (const float*)d_in[14];
    const float* b1   = (const float*)d_in[15];
    const float* w2   = (const float*)d_in[16];
    const float* b2   = (const float*)d_in[17];
    float* out = (float*)d_out;

    cudaFuncSetAttribute(k_qkv_mma,   cudaFuncAttributeMaxDynamicSharedMemorySize, SMEM_MMA);
    cudaFuncSetAttribute(k_qkv_bot,   cudaFuncAttributeMaxDynamicSharedMemorySize, SMEM_MMA);
    cudaFuncSetAttribute(k_scores_sm, cudaFuncAttributeMaxDynamicSharedMemorySize, SMEM_MMA);
    cudaFuncSetAttribute(k_pv_mma,    cudaFuncAttributeMaxDynamicSharedMemorySize, SMEM_MMA);

    k_prep<<<(unsigned)((PR3 + 255) / 256), 256>>>(subj, obj, rel, ent, relw, time, q_w, k_w, v_w);
    k_gemm_x<<<dim3(DM / 128, ROWS / 128), 256>>>(in_w, in_b);

    for (int h = 0; h < 2; h++) {
        for (int l = 0; l < 2; l++) {
            int hl = h * 2 + l;
            if (l == 0) {
                k_qkv_mma<<<dim3(6, N_SEQ), 256, SMEM_MMA>>>(q_b, k_b, v_b, hl, 1);
                k_qkv_bot<<<dim3(6, N_SEQ), 256, SMEM_MMA>>>(q_b, k_b, v_b, hl);
            } else {
                k_qkv_mma<<<dim3(6, ROWS2 / 128), 256, SMEM_MMA>>>(q_b, k_b, v_b, hl, 0);
            }
            k_vt<<<dim3(8, N_SEQ), 256>>>();
            k_sv<<<N_SEQ, 256>>>();
            k_scores_sm<<<dim3(2, N_SEQ), 256, SMEM_MMA>>>(time);
            k_pv_mma<<<dim3(2, 2, N_SEQ), 256, SMEM_MMA>>>();
            int it = h * 2 + l;
            k_update_ci<<<(ROWS * DM + 255) / 256, 256>>>(time, h, it < 3 ? 1 : 0, l == 0 ? 1 : 0);
        }
    }
    k_head<<<N_SEQ, 256>>>(w1, b1, w2, b2, out);
}

// round 15
// speedup vs baseline: 1.2890x; 1.2254x over previous
#include <cuda_runtime.h>
#include <cuda_bf16.h>
#include <math.h>
#include <stdint.h>

#define N_SEQ 512
#define LEN   128
#define LL2   256
#define DM    256
#define DT    32
#define DIN   288
#define KP    288
#define KE    384
#define ROWS  (N_SEQ*LEN)   // 65536
#define ROWS2 (N_SEQ*LL2)   // 131072

#define TILE_B   10240               // 128 rows * 80 bytes
#define SMEM_MMA (8 * TILE_B)        // 81920

// ---------------- scratch ----------------------------------------------------
__device__ float g_emb[ROWS*KE];
__device__ float g_cur[2][ROWS*DM];
__device__ __nv_bfloat16 g_cih[(size_t)ROWS2*KP];
__device__ __nv_bfloat16 g_cil[(size_t)ROWS2*KP];
__device__ __nv_bfloat16 g_temh[ROWS*DT];
__device__ __nv_bfloat16 g_teml[ROWS*DT];
__device__ __nv_bfloat16 g_wTh[3*4*256*KP];
__device__ __nv_bfloat16 g_wTl[3*4*256*KP];
__device__ __nv_bfloat16 g_qh[(size_t)ROWS2*DM];
__device__ __nv_bfloat16 g_ql[(size_t)ROWS2*DM];
__device__ __nv_bfloat16 g_kh[(size_t)ROWS2*DM];
__device__ __nv_bfloat16 g_kl[(size_t)ROWS2*DM];
__device__ float g_v[ROWS2*DM];
__device__ __nv_bfloat16 g_vTh[(size_t)N_SEQ*DM*LEN];
__device__ __nv_bfloat16 g_vTl[(size_t)N_SEQ*DM*LEN];
__device__ __nv_bfloat16 g_ph[(size_t)N_SEQ*LL2*LEN];
__device__ __nv_bfloat16 g_pl[(size_t)N_SEQ*LL2*LEN];
__device__ float g_pd[N_SEQ*LL2];
__device__ float g_sv[N_SEQ*DM];
__device__ float g_o[ROWS2*DM];

// ---------------- helpers -----------------------------------------------------
__device__ __forceinline__ uint32_t smem_u32(const void* p) {
    uint32_t a;
    asm("{ .reg .u64 t; cvta.to.shared.u64 t, %1; cvt.u32.u64 %0, t; }" : "=r"(a) : "l"(p));
    return a;
}
#define LDSM4(r0, r1, r2, r3, addr) \
    asm volatile("ldmatrix.sync.aligned.m8n8.x4.shared.b16 {%0,%1,%2,%3}, [%4];" \
        : "=r"(r0), "=r"(r1), "=r"(r2), "=r"(r3) : "r"(addr))
#define MMA16816(c, a, b0, b1) \
    asm volatile("mma.sync.aligned.m16n8k16.row.col.f32.bf16.bf16.f32 " \
        "{%0,%1,%2,%3},{%4,%5,%6,%7},{%8,%9},{%0,%1,%2,%3};" \
        : "+f"((c)[0]), "+f"((c)[1]), "+f"((c)[2]), "+f"((c)[3]) \
        : "r"((a)[0]), "r"((a)[1]), "r"((a)[2]), "r"((a)[3]), "r"(b0), "r"(b1))
#define CPASYNC16(dst, src) \
    asm volatile("cp.async.ca.shared.global [%0], [%1], 16;" :: "r"(dst), "l"(src))
#define CPCOMMIT() asm volatile("cp.async.commit_group;" ::: "memory")
#define CPWAIT0()  asm volatile("cp.async.wait_group 0;" ::: "memory")
#define CPWAIT1()  asm volatile("cp.async.wait_group 1;" ::: "memory")

__device__ __forceinline__ void split_store(__nv_bfloat16* ph, __nv_bfloat16* pl,
                                            size_t idx, float v) {
    __nv_bfloat16 hi = __float2bfloat16(v);
    ph[idx] = hi;
    pl[idx] = __float2bfloat16(v - __bfloat162float(hi));
}

// ---------------- fused 3-term mma core ---------------------------------------
__device__ __forceinline__ void mma_core3(
    const __nv_bfloat16* Ah, const __nv_bfloat16* Al,
    const __nv_bfloat16* Bh, const __nv_bfloat16* Bl,
    int lda, int ldb, int nkt, uint32_t sbase, float acc[4][4][4])
{
    int tid = threadIdx.x;
    int w = tid >> 5, lane = tid & 31;
    int wm = (w & 1) << 6;
    int wn = (w >> 1) << 5;
    int lr = tid >> 1;
    int c2 = (tid & 1) << 1;

    const char* pAh = (const char*)(Ah + (size_t)lr * lda) + c2 * 16;
    const char* pAl = (const char*)(Al + (size_t)lr * lda) + c2 * 16;
    const char* pBh = (const char*)(Bh + (size_t)lr * ldb) + c2 * 16;
    const char* pBl = (const char*)(Bl + (size_t)lr * ldb) + c2 * 16;
    uint32_t sdst = sbase + lr * 80 + c2 * 16;

    {
        CPASYNC16(sdst,              pAh);       CPASYNC16(sdst + 16,              pAh + 16);
        CPASYNC16(sdst + TILE_B,     pAl);       CPASYNC16(sdst + TILE_B + 16,     pAl + 16);
        CPASYNC16(sdst + 2*TILE_B,   pBh);       CPASYNC16(sdst + 2*TILE_B + 16,   pBh + 16);
        CPASYNC16(sdst + 3*TILE_B,   pBl);       CPASYNC16(sdst + 3*TILE_B + 16,   pBl + 16);
        CPCOMMIT();
    }

    int buf = 0;
    for (int kt = 0; kt < nkt; kt++) {
        bool more = (kt + 1 < nkt);
        if (more) {
            int off = (kt + 1) * 64;
            uint32_t d = sdst + (buf ^ 1) * (4 * TILE_B);
            CPASYNC16(d,              pAh + off);       CPASYNC16(d + 16,              pAh + off + 16);
            CPASYNC16(d + TILE_B,     pAl + off);       CPASYNC16(d + TILE_B + 16,     pAl + off + 16);
            CPASYNC16(d + 2*TILE_B,   pBh + off);       CPASYNC16(d + 2*TILE_B + 16,   pBh + off + 16);
            CPASYNC16(d + 3*TILE_B,   pBl + off);       CPASYNC16(d + 3*TILE_B + 16,   pBl + off + 16);
            CPCOMMIT();
            CPWAIT1();
        } else {
            CPWAIT0();
        }
        __syncthreads();

        uint32_t bAh = sbase + buf * (4 * TILE_B);
        uint32_t bAl = bAh + TILE_B;
        uint32_t bBh = bAh + 2 * TILE_B;
        uint32_t bBl = bAh + 3 * TILE_B;
#pragma unroll
        for (int ks = 0; ks < 2; ks++) {
            uint32_t arow = (uint32_t)((lane & 15)) * 80 + (uint32_t)(ks * 2 + ((lane >> 4) & 1)) * 16;
            uint32_t brow = (uint32_t)((lane & 7) + ((lane >> 4) & 1) * 8) * 80
                          + (uint32_t)(ks * 2 + ((lane >> 3) & 1)) * 16;
            uint32_t bh[2][4], bl[2][4];
#pragma unroll
            for (int p = 0; p < 2; p++) {
                uint32_t ad = (uint32_t)(wn + p * 16) * 80 + brow;
                LDSM4(bh[p][0], bh[p][1], bh[p][2], bh[p][3], bBh + ad);
                LDSM4(bl[p][0], bl[p][1], bl[p][2], bl[p][3], bBl + ad);
            }
            uint32_t a[4][4];
#pragma unroll
            for (int mf = 0; mf < 4; mf++) {
                uint32_t ad = (uint32_t)(wm + mf * 16) * 80 + arow;
                LDSM4(a[mf][0], a[mf][1], a[mf][2], a[mf][3], bAh + ad);
            }
#pragma unroll
            for (int mf = 0; mf < 4; mf++)
#pragma unroll
                for (int nf = 0; nf < 4; nf++) {
                    MMA16816(acc[mf][nf], a[mf], bh[nf >> 1][(nf & 1) * 2], bh[nf >> 1][(nf & 1) * 2 + 1]);
                    MMA16816(acc[mf][nf], a[mf], bl[nf >> 1][(nf & 1) * 2], bl[nf >> 1][(nf & 1) * 2 + 1]);
                }
#pragma unroll
            for (int mf = 0; mf < 4; mf++) {
                uint32_t ad = (uint32_t)(wm + mf * 16) * 80 + arow;
                LDSM4(a[mf][0], a[mf][1], a[mf][2], a[mf][3], bAl + ad);
            }
#pragma unroll
            for (int mf = 0; mf < 4; mf++)
#pragma unroll
                for (int nf = 0; nf < 4; nf++)
                    MMA16816(acc[mf][nf], a[mf], bh[nf >> 1][(nf & 1) * 2], bh[nf >> 1][(nf & 1) * 2 + 1]);
        }
        __syncthreads();
        buf ^= 1;
    }
}

// ---------------- QKV epilogue -------------------------------------------------
__device__ __forceinline__ void qkv_epilogue(float acc[4][4][4], int z, int baseRow,
                                             int n0, const float* bias) {
    int w = threadIdx.x >> 5, lane = threadIdx.x & 31;
    int wm = (w & 1) << 6, wn = (w >> 1) << 5;
    int r0 = lane >> 2, c0 = (lane & 3) << 1;
#pragma unroll
    for (int mf = 0; mf < 4; mf++)
#pragma unroll
        for (int nf = 0; nf < 4; nf++) {
            int row = baseRow + wm + mf * 16 + r0;
            int col = n0 + wn + nf * 8 + c0;
#pragma unroll
            for (int q = 0; q < 4; q++) {
                size_t idx = (size_t)(row + (q >> 1) * 8) * DM + col + (q & 1);
                float val = acc[mf][nf][q] + bias[col + (q & 1)];
                if (z == 2) g_v[idx] = val;
                else if (z == 0) split_store(g_qh, g_ql, idx, val);
                else             split_store(g_kh, g_kl, idx, val);
            }
        }
}

// ---------------- fused prep ---------------------------------------------------
#define PR0 ((size_t)ROWS*KE)
#define PR1 (PR0 + (size_t)ROWS*16)
#define PR2 (PR1 + (size_t)2*ROWS*DM)
#define PR3 (PR2 + (size_t)3*4*256*KP)
__global__ void k_prep(const int* __restrict__ subj, const int* __restrict__ obj,
                       const int* __restrict__ rel, const float* __restrict__ ent,
                       const float* __restrict__ relw, const float* __restrict__ time,
                       const float* __restrict__ qw, const float* __restrict__ kw,
                       const float* __restrict__ vw) {
    size_t i = (size_t)blockIdx.x * 256 + threadIdx.x;
    if (i < PR0) {
        int row = (int)(i / KE);
        int c   = (int)(i - (size_t)row * KE);
        float v;
        if (c < 128)      v = ent[subj[row] * 128 + c];
        else if (c < 256) v = ent[obj[row] * 128 + (c - 128)];
        else              v = relw[rel[row] * 128 + (c - 256)];
        g_emb[i] = v;
    } else if (i < PR1) {
        size_t j = i - PR0;
        int row = (int)(j >> 4);
        int f   = (int)(j & 15);
        float t = time[row];
        float div = expf((float)(2 * f) * -0.28782313662425576f);
        float arg = t * div;
        float np  = (t > 0.f) ? 1.f : 0.f;
        float s = sinf(arg) * np;
        float c = cosf(arg) * np;
        int n = row >> 7, l = row & 127;
        size_t rT = ((size_t)n * LL2 + l) * KP + 256 + 2 * f;
        size_t rB = rT + (size_t)128 * KP;
        split_store(g_cih, g_cil, rT, s);
        split_store(g_cih, g_cil, rT + 1, c);
        split_store(g_cih, g_cil, rB, s);
        split_store(g_cih, g_cil, rB + 1, c);
        split_store(g_temh, g_teml, (size_t)row * DT + 2 * f, s);
        split_store(g_temh, g_teml, (size_t)row * DT + 2 * f + 1, c);
    } else if (i < PR2) {
        ((float*)g_cur)[i - PR1] = 0.f;
    } else if (i < PR3) {
        size_t j = i - PR2;
        int k  = (int)(j % KP);
        int n  = (int)((j / KP) & 255);
        int hl = (int)((j / (KP * 256)) & 3);
        int z  = (int)(j / ((size_t)KP * 256 * 4));
        const float* W = (z == 0) ? qw : (z == 1) ? kw : vw;
        float v = W[(hl * DIN + k) * 256 + n];
        split_store(g_wTh, g_wTl, j, v);
    }
}

// ---------------- QKV mma, mode-dispatched -------------------------------------
// mode 1: top rows, all z (grid 6, N_SEQ)
// mode 2: top rows, z in {1,2}   (grid 4, N_SEQ)
// mode 3: bottom rows, z=2 only  (grid 2, N_SEQ)
__global__ __launch_bounds__(256, 2) void k_qkv_mma(const float* __restrict__ qb,
                                                    const float* __restrict__ kb,
                                                    const float* __restrict__ vb,
                                                    int hl, int mode) {
    extern __shared__ __nv_bfloat16 smem_dyn[];
    uint32_t sbase = smem_u32(smem_dyn);
    int z, n0, m0;
    if (mode == 1)      { z = blockIdx.x >> 1;       n0 = (blockIdx.x & 1) << 7; m0 = blockIdx.y << 8; }
    else if (mode == 2) { z = 1 + (blockIdx.x >> 1); n0 = (blockIdx.x & 1) << 7; m0 = blockIdx.y << 8; }
    else                { z = 2;                     n0 = blockIdx.x << 7;       m0 = (blockIdx.y << 8) + 128; }

    float acc[4][4][4] = {};
    mma_core3(g_cih + (size_t)m0 * KP, g_cil + (size_t)m0 * KP,
              g_wTh + ((size_t)(z * 4 + hl) * 256 + n0) * KP,
              g_wTl + ((size_t)(z * 4 + hl) * 256 + n0) * KP,
              KP, KP, 9, sbase, acc);
    qkv_epilogue(acc, z, m0, n0, ((z == 0) ? qb : (z == 1) ? kb : vb) + hl * 256);
}

// ---------------- QKV bottom fast path at l=0: K=32 (tem only) -----------------
__global__ __launch_bounds__(256, 2) void k_qkv_bot(const float* __restrict__ qb,
                                                    const float* __restrict__ kb,
                                                    const float* __restrict__ vb, int hl) {
    extern __shared__ __nv_bfloat16 smem_dyn[];
    uint32_t sbase = smem_u32(smem_dyn);
    int z  = blockIdx.x >> 1;
    int n0 = (blockIdx.x & 1) << 7;
    int n  = blockIdx.y;

    float acc[4][4][4] = {};
    mma_core3(g_temh + (size_t)n * 128 * DT, g_teml + (size_t)n * 128 * DT,
              g_wTh + ((size_t)(z * 4 + hl) * 256 + n0) * KP + 256,
              g_wTl + ((size_t)(z * 4 + hl) * 256 + n0) * KP + 256,
              DT, KP, 1, sbase, acc);
    qkv_epilogue(acc, z, n * LL2 + 128, n0, ((z == 0) ? qb : (z == 1) ? kb : vb) + hl * 256);
}

// ---------------- V transpose + sv ---------------------------------------------
__global__ __launch_bounds__(256) void k_vt() {
    __shared__ float tile[128][33];
    int n = blockIdx.y, d0 = blockIdx.x << 5;
    for (int el = threadIdx.x; el < 4096; el += 256) {
        int key = el >> 5, d = el & 31;
        tile[key][d] = g_v[((size_t)n * LL2 + key) * DM + d0 + d];
    }
    __syncthreads();
    for (int el = threadIdx.x; el < 4096; el += 256) {
        int d = el >> 7, key = el & 127;
        size_t o = (size_t)n * DM * LEN + (size_t)(d0 + d) * LEN + key;
        split_store(g_vTh, g_vTl, o, tile[key][d]);
    }
}

__global__ void k_sv() {
    int n = blockIdx.x;
    int d = threadIdx.x;
    const float* vp = g_v + (n * LL2 + LEN) * DM + d;
    float s = 0.f;
#pragma unroll 8
    for (int j = 0; j < LEN; j++) s += vp[j * DM];
    g_sv[n * DM + d] = s;
}

// ---------------- fused scores mma + masked softmax ----------------------------
__global__ __launch_bounds__(256, 2) void k_scores_sm(const float* __restrict__ time) {
    extern __shared__ __nv_bfloat16 smem_dyn[];
    uint32_t sbase = smem_u32(smem_dyn);
    int n  = blockIdx.y;
    int m0 = blockIdx.x << 7;

    float acc[4][4][4] = {};
    mma_core3(g_qh + ((size_t)n * LL2 + m0) * DM, g_ql + ((size_t)n * LL2 + m0) * DM,
              g_kh + (size_t)n * LL2 * DM, g_kl + (size_t)n * LL2 * DM,
              DM, DM, 8, sbase, acc);

    float* P = (float*)smem_dyn;
    const int LDP = 132;
    float* stt = P + 128 * LDP;
    int w = threadIdx.x >> 5, lane = threadIdx.x & 31;
    int wm = (w & 1) << 6, wn = (w >> 1) << 5;
    int r0 = lane >> 2, c0 = (lane & 3) << 1;
#pragma unroll
    for (int mf = 0; mf < 4; mf++)
#pragma unroll
        for (int nf = 0; nf < 4; nf++) {
            int row = wm + mf * 16 + r0;
            int col = wn + nf * 8 + c0;
            P[row * LDP + col]           = acc[mf][nf][0] * 0.0625f;
            P[row * LDP + col + 1]       = acc[mf][nf][1] * 0.0625f;
            P[(row + 8) * LDP + col]     = acc[mf][nf][2] * 0.0625f;
            P[(row + 8) * LDP + col + 1] = acc[mf][nf][3] * 0.0625f;
        }
    if (threadIdx.x < 128) stt[threadIdx.x] = time[n * LEN + threadIdx.x];
    __syncthreads();

    bool bottom = (m0 == LEN);
    for (int rr = 0; rr < 16; rr++) {
        int r = w * 16 + rr;
        int rowId = n * LL2 + m0 + r;
        __nv_bfloat16* oh = g_ph + (size_t)rowId * LEN;
        __nv_bfloat16* ol = g_pl + (size_t)rowId * LEN;

        float vals[4];
        float mx = -1e30f;
#pragma unroll
        for (int c = 0; c < 4; c++) {
            int j = lane + c * 32;
            float s = P[r * LDP + j];
            bool masked = (j >= r) || (stt[j] == 0.f);
            s = masked ? -1e9f : s;
            vals[c] = s;
            mx = fmaxf(mx, s);
        }
        float d = 0.f;
        if (bottom) {
            size_t base = (size_t)(n * LL2 + LEN + r) * DM / 2;
            const __nv_bfloat162* qh2 = (const __nv_bfloat162*)g_qh + base;
            const __nv_bfloat162* ql2 = (const __nv_bfloat162*)g_ql + base;
            const __nv_bfloat162* kh2 = (const __nv_bfloat162*)g_kh + base;
            const __nv_bfloat162* kl2 = (const __nv_bfloat162*)g_kl + base;
#pragma unroll
            for (int c = 0; c < 4; c++) {
                int idx = lane * 4 + c;
                __nv_bfloat162 a = qh2[idx], b = ql2[idx], e = kh2[idx], f = kl2[idx];
                float qx = __bfloat162float(a.x) + __bfloat162float(b.x);
                float qy = __bfloat162float(a.y) + __bfloat162float(b.y);
                float kx = __bfloat162float(e.x) + __bfloat162float(f.x);
                float ky = __bfloat162float(e.y) + __bfloat162float(f.y);
                d += qx * kx + qy * ky;
            }
#pragma unroll
            for (int off = 16; off; off >>= 1) d += __shfl_xor_sync(0xffffffffu, d, off);
            d *= 0.0625f;
        }
#pragma unroll
        for (int off = 16; off; off >>= 1) mx = fmaxf(mx, __shfl_xor_sync(0xffffffffu, mx, off));

        if (!bottom && mx < -5e8f) {
            __nv_bfloat16 u = __float2bfloat16(1.0f / 256.0f);
#pragma unroll
            for (int c = 0; c < 4; c++) { oh[lane + c * 32] = u; ol[lane + c * 32] = __float2bfloat16(0.f); }
            if (lane == 0) g_pd[rowId] = 1.0f / 256.0f;
            continue;
        }
        if (bottom) mx = fmaxf(mx, d);
        float sum = 0.f;
#pragma unroll
        for (int c = 0; c < 4; c++) { vals[c] = expf(vals[c] - mx); sum += vals[c]; }
#pragma unroll
        for (int off = 16; off; off >>= 1) sum += __shfl_xor_sync(0xffffffffu, sum, off);
        float ed = bottom ? expf(d - mx) : 0.f;
        float inv = 1.f / (sum + ed);
#pragma unroll
        for (int c = 0; c < 4; c++) {
            float p = vals[c] * inv;
            __nv_bfloat16 hi = __float2bfloat16(p);
            oh[lane + c * 32] = hi;
            ol[lane + c * 32] = __float2bfloat16(p - __bfloat162float(hi));
        }
        if (lane == 0) g_pd[rowId] = ed * inv;
    }
}

// ---------------- PV mma -------------------------------------------------------
__global__ __launch_bounds__(256, 2) void k_pv_mma() {
    extern __shared__ __nv_bfloat16 smem_dyn[];
    uint32_t sbase = smem_u32(smem_dyn);
    int n  = blockIdx.z;
    int m0 = blockIdx.y << 7;
    int n0 = blockIdx.x << 7;

    float acc[4][4][4] = {};
    mma_core3(g_ph + ((size_t)n * LL2 + m0) * LEN, g_pl + ((size_t)n * LL2 + m0) * LEN,
              g_vTh + ((size_t)n * DM + n0) * LEN, g_vTl + ((size_t)n * DM + n0) * LEN,
              LEN, LEN, 4, sbase, acc);

    int w = threadIdx.x >> 5, lane = threadIdx.x & 31;
    int wm = (w & 1) << 6, wn = (w >> 1) << 5;
    int r0 = lane >> 2, c0 = (lane & 3) << 1;
    const float* V = g_v + (size_t)n * LL2 * DM;
    float* O = g_o + (size_t)n * LL2 * DM;
#pragma unroll
    for (int mf = 0; mf < 4; mf++)
#pragma unroll
        for (int nf = 0; nf < 4; nf++) {
            int row = m0 + wm + mf * 16 + r0;
            int col = n0 + wn + nf * 8 + c0;
#pragma unroll
            for (int q = 0; q < 4; q++) {
                int r = row + (q >> 1) * 8;
                int c = col + (q & 1);
                float pd = g_pd[n * LL2 + r];
                float extra = (r < LEN) ? g_sv[n * DM + c] : V[(size_t)r * DM + c];
                O[(size_t)r * DM + c] = acc[mf][nf][q] + pd * extra;
            }
        }
}

// ---------------- residual update + next-iter ci -------------------------------
__global__ void k_update_ci(const float* __restrict__ time, int h,
                            int writeTop, int writeBottom, int updCur) {
    int i = blockIdx.x * 256 + threadIdx.x;
    if (i >= ROWS * DM) return;
    int row = i >> 8;
    int d   = i & 255;
    int n   = row >> 7;
    int l   = row & 127;
    if (updCur) {
        float bot = g_o[(n * LL2 + LEN + l) * DM + d];
        float np  = (time[row] > 0.f) ? 1.f : 0.f;
        float nc  = g_cur[h][i] + tanhf(bot * np);
        g_cur[h][i] = nc;
        if (writeBottom)
            split_store(g_cih, g_cil, ((size_t)n * LL2 + LEN + l) * KP + d, nc);
    }
    if (writeTop) {
        float top = g_o[(n * LL2 + l) * DM + d];
        split_store(g_cih, g_cil, ((size_t)n * LL2 + l) * KP + d, top);
    }
}

// ---------------- last-row attention (l=1): cur[h][:,127] only -----------------
__global__ __launch_bounds__(256) void k_last(const float* __restrict__ time,
                                              const float* __restrict__ qb,
                                              const float* __restrict__ kb,
                                              const float* __restrict__ vb,
                                              int h, int hl) {
    __shared__ float ci[KP];
    __shared__ float qv[256], kv2[256], vv2[256];
    __shared__ float sp[128];
    __shared__ float spd[1];
    int n = blockIdx.x, t = threadIdx.x;
    int w = t >> 5, lane = t & 31;

    size_t rb = ((size_t)n * LL2 + 255) * KP;
    for (int kk = t; kk < KP; kk += 256)
        ci[kk] = __bfloat162float(g_cih[rb + kk]) + __bfloat162float(g_cil[rb + kk]);
    __syncthreads();

    // q/k/v projections for row 255: 768 warp-dots over K=288
    for (int idx = w; idx < 768; idx += 8) {
        int z = idx >> 8, d = idx & 255;
        const __nv_bfloat16* wh = g_wTh + ((size_t)(z * 4 + hl) * 256 + d) * KP;
        const __nv_bfloat16* wl = g_wTl + ((size_t)(z * 4 + hl) * 256 + d) * KP;
        float s = 0.f;
        for (int kk = lane; kk < KP; kk += 32)
            s += ci[kk] * (__bfloat162float(wh[kk]) + __bfloat162float(wl[kk]));
#pragma unroll
        for (int o = 16; o; o >>= 1) s += __shfl_xor_sync(0xffffffffu, s, o);
        if (lane == 0) {
            if (z == 0)      qv[d]  = s + qb[hl * 256 + d];
            else if (z == 1) kv2[d] = s + kb[hl * 256 + d];
            else             vv2[d] = s + vb[hl * 256 + d];
        }
    }
    __syncthreads();

    // scores vs 128 top keys
    const float* tt = time + n * LEN;
    for (int j = w; j < 128; j += 8) {
        const __nv_bfloat16* kh = g_kh + ((size_t)n * LL2 + j) * DM;
        const __nv_bfloat16* kl = g_kl + ((size_t)n * LL2 + j) * DM;
        float s = 0.f;
        for (int d = lane; d < 256; d += 32)
            s += qv[d] * (__bfloat162float(kh[d]) + __bfloat162float(kl[d]));
#pragma unroll
        for (int o = 16; o; o >>= 1) s += __shfl_xor_sync(0xffffffffu, s, o);
        if (lane == 0) {
            bool masked = (j >= 127) || (tt[j] == 0.f);
            sp[j] = masked ? -1e9f : s * 0.0625f;
        }
    }
    __syncthreads();

    // diag + softmax on warp 0
    if (w == 0) {
        float dd = 0.f;
        for (int d = lane; d < 256; d += 32) dd += qv[d] * kv2[d];
#pragma unroll
        for (int o = 16; o; o >>= 1) dd += __shfl_xor_sync(0xffffffffu, dd, o);
        dd *= 0.0625f;

        float vals[4];
        float mx = dd;
#pragma unroll
        for (int c = 0; c < 4; c++) { vals[c] = sp[lane + c * 32]; mx = fmaxf(mx, vals[c]); }
#pragma unroll
        for (int o = 16; o; o >>= 1) mx = fmaxf(mx, __shfl_xor_sync(0xffffffffu, mx, o));
        float sum = 0.f;
#pragma unroll
        for (int c = 0; c < 4; c++) { vals[c] = expf(vals[c] - mx); sum += vals[c]; }
#pragma unroll
        for (int o = 16; o; o >>= 1) sum += __shfl_xor_sync(0xffffffffu, sum, o);
        float ed = expf(dd - mx);
        float inv = 1.f / (sum + ed);
#pragma unroll
        for (int c = 0; c < 4; c++) sp[lane + c * 32] = vals[c] * inv;
        if (lane == 0) spd[0] = ed * inv;
    }
    __syncthreads();

    // O row + residual, thread t = dim
    float o = 0.f;
    const float* V = g_v + (size_t)n * LL2 * DM + t;
    for (int j = 0; j < 128; j++) o += sp[j] * V[(size_t)j * DM];
    o += spd[0] * vv2[t];
    float np = (tt[127] > 0.f) ? 1.f : 0.f;
    g_cur[h][((size_t)n * LEN + 127) * DM + t] += tanhf(o * np);
}

// ---------------- FFMA GEMM for input projection (writes ci) -------------------
__device__ __forceinline__ void gemm_compute(const float (*As)[140], const float (*Bs)[128],
                                             float acc[8][8], int tx, int ty) {
#pragma unroll
    for (int k = 0; k < 8; k++) {
        float a[8], b[8];
        *(float4*)(a)     = *(const float4*)&As[k][ty * 4];
        *(float4*)(a + 4) = *(const float4*)&As[k][64 + ty * 4];
        *(float4*)(b)     = *(const float4*)&Bs[k][tx * 4];
        *(float4*)(b + 4) = *(const float4*)&Bs[k][64 + tx * 4];
#pragma unroll
        for (int i = 0; i < 8; i++)
#pragma unroll
            for (int j = 0; j < 8; j++)
                acc[i][j] += a[i] * b[j];
    }
}

__global__ __launch_bounds__(256) void k_gemm_x(const float* __restrict__ W,
                                                const float* __restrict__ bias) {
    __shared__ float As[2][8][140];
    __shared__ float Bs[2][8][128];
    float acc[8][8] = {};
    int m0 = blockIdx.y << 7, n0 = blockIdx.x << 7;
    int tid = threadIdx.x;
    int tx = tid & 15, ty = tid >> 4;
    int ar = tid >> 1, kg = (tid & 1) << 2;
    int br = tid >> 5, bc = (tid & 31) << 2;

    float4 a = *(const float4*)(g_emb + (m0 + ar) * KE + kg);
    float4 b = *(const float4*)(W + br * DM + n0 + bc);
    As[0][kg][ar] = a.x; As[0][kg + 1][ar] = a.y; As[0][kg + 2][ar] = a.z; As[0][kg + 3][ar] = a.w;
    *(float4*)&Bs[0][br][bc] = b;
    __syncthreads();

    int buf = 0;
    for (int k0 = 8; k0 < KE; k0 += 8) {
        float4 an = *(const float4*)(g_emb + (m0 + ar) * KE + k0 + kg);
        float4 bn = *(const float4*)(W + (k0 + br) * DM + n0 + bc);
        gemm_compute(As[buf], Bs[buf], acc, tx, ty);
        int nb = buf ^ 1;
        As[nb][kg][ar] = an.x; As[nb][kg + 1][ar] = an.y; As[nb][kg + 2][ar] = an.z; As[nb][kg + 3][ar] = an.w;
        *(float4*)&Bs[nb][br][bc] = bn;
        __syncthreads();
        buf = nb;
    }
    gemm_compute(As[buf], Bs[buf], acc, tx, ty);

#pragma unroll
    for (int i = 0; i < 8; i++) {
        int r = m0 + ((i < 4) ? (ty << 2) + i : 64 + (ty << 2) + i - 4);
        int n = r >> 7, l = r & 127;
#pragma unroll
        for (int j = 0; j < 8; j++) {
            int c = n0 + ((j < 4) ? (tx << 2) + j : 64 + (tx << 2) + j - 4);
            split_store(g_cih, g_cil, ((size_t)n * LL2 + l) * KP + c, acc[i][j] + bias[c]);
        }
    }
}

// ---------------- final MLP head -----------------------------------------------
__global__ __launch_bounds__(256) void k_head(const float* __restrict__ w1,
                                              const float* __restrict__ b1,
                                              const float* __restrict__ w2,
                                              const float* __restrict__ b2,
                                              float* __restrict__ out) {
    int n = blockIdx.x;
    int t = threadIdx.x;
    __shared__ float sl[512];
    __shared__ float sh[256];
    sl[t]       = g_cur[0][(n * LEN + LEN - 1) * DM + t];
    sl[256 + t] = g_cur[1][(n * LEN + LEN - 1) * DM + t];
    __syncthreads();
    float acc = b1[t];
    for (int k = 0; k < 512; k++) acc += sl[k] * w1[k * DM + t];
    float x = acc;
    float g = 0.5f * x * (1.f + erff(x * 0.7071067811865476f));
    sh[t] = g * w2[t];
    __syncthreads();
    for (int s = 128; s > 0; s >>= 1) {
        if (t < s) sh[t] += sh[t + s];
        __syncthreads();
    }
    if (t == 0) out[n] = sh[0] + b2[0];
}

// ---------------- launch --------------------------------------------------------
extern "C" void kernel_launch(void* const* d_in, const int* in_sizes, int n_in,
                              void* d_out, int out_size) {
    const int*   subj = (const int*)d_in[0];
    const int*   obj  = (const int*)d_in[1];
    const int*   rel  = (const int*)d_in[2];
    const float* time = (const float*)d_in[3];
    const float* ent  = (const float*)d_in[4];
    const float* relw = (const float*)d_in[5];
    const float* in_w = (const float*)d_in[6];
    const float* in_b = (const float*)d_in[7];
    const float* q_w  = (const float*)d_in[8];
    const float* q_b  = (const float*)d_in[9];
    const float* k_w  = (const float*)d_in[10];
    const float* k_b  = (const float*)d_in[11];
    const float* v_w  = (const float*)d_in[12];
    const float* v_b  = (const float*)d_in[13];
    const float* w1   = (const float*)d_in[14];
    const float* b1   = (const float*)d_in[15];
    const float* w2   = (const float*)d_in[16];
    const float* b2   = (const float*)d_in[17];
    float* out = (float*)d_out;

    cudaFuncSetAttribute(k_qkv_mma,   cudaFuncAttributeMaxDynamicSharedMemorySize, SMEM_MMA);
    cudaFuncSetAttribute(k_qkv_bot,   cudaFuncAttributeMaxDynamicSharedMemorySize, SMEM_MMA);
    cudaFuncSetAttribute(k_scores_sm, cudaFuncAttributeMaxDynamicSharedMemorySize, SMEM_MMA);
    cudaFuncSetAttribute(k_pv_mma,    cudaFuncAttributeMaxDynamicSharedMemorySize, SMEM_MMA);

    k_prep<<<(unsigned)((PR3 + 255) / 256), 256>>>(subj, obj, rel, ent, relw, time, q_w, k_w, v_w);
    k_gemm_x<<<dim3(DM / 128, ROWS / 128), 256>>>(in_w, in_b);

    for (int h = 0; h < 2; h++) {
        for (int l = 0; l < 2; l++) {
            int hl = h * 2 + l;
            if (l == 0) {
                // full layer: top QKV + tem-only bottom QKV, full attention
                k_qkv_mma<<<dim3(6, N_SEQ), 256, SMEM_MMA>>>(q_b, k_b, v_b, hl, 1);
                k_qkv_bot<<<dim3(6, N_SEQ), 256, SMEM_MMA>>>(q_b, k_b, v_b, hl);
                k_vt<<<dim3(8, N_SEQ), 256>>>();
                k_sv<<<N_SEQ, 256>>>();
                k_scores_sm<<<dim3(2, N_SEQ), 256, SMEM_MMA>>>(time);
                k_pv_mma<<<dim3(2, 2, N_SEQ), 256, SMEM_MMA>>>();
                k_update_ci<<<(ROWS * DM + 255) / 256, 256>>>(time, h, 1, 1, 1);
            } else if (h == 0) {
                // h0,l1: top output fully needed (feeds h1); bottom -> row 127 only
                k_qkv_mma<<<dim3(6, N_SEQ), 256, SMEM_MMA>>>(q_b, k_b, v_b, hl, 1);
                k_qkv_mma<<<dim3(2, N_SEQ), 256, SMEM_MMA>>>(q_b, k_b, v_b, hl, 3); // bottom V for sv
                k_vt<<<dim3(8, N_SEQ), 256>>>();
                k_sv<<<N_SEQ, 256>>>();
                k_scores_sm<<<dim3(1, N_SEQ), 256, SMEM_MMA>>>(time);               // top tile only
                k_pv_mma<<<dim3(2, 1, N_SEQ), 256, SMEM_MMA>>>();                   // top O only
                k_update_ci<<<(ROWS * DM + 255) / 256, 256>>>(time, h, 1, 0, 0);    // ci top only
                k_last<<<N_SEQ, 256>>>(time, q_b, k_b, v_b, h, hl);
            } else {
                // h1,l1: everything dead except cur[1][:,127]
                k_qkv_mma<<<dim3(4, N_SEQ), 256, SMEM_MMA>>>(q_b, k_b, v_b, hl, 2); // top k,v only
                k_last<<<N_SEQ, 256>>>(time, q_b, k_b, v_b, h, hl);
            }
        }
    }
    k_head<<<N_SEQ, 256>>>(w1, b1, w2, b2, out);
}

// round 17
// speedup vs baseline: 1.2925x; 1.0026x over previous
#include <cuda_runtime.h>
#include <cuda_bf16.h>
#include <math.h>
#include <stdint.h>

#define N_SEQ 512
#define LEN   128
#define LL2   256
#define DM    256
#define DT    32
#define DIN   288
#define KP    288
#define KE    384
#define ROWS  (N_SEQ*LEN)   // 65536
#define ROWS2 (N_SEQ*LL2)   // 131072

#define TILE_B   10240               // 128 rows * 80 bytes
#define SMEM_MMA (8 * TILE_B)        // 81920

// ---------------- scratch ----------------------------------------------------
__device__ float g_emb[ROWS*KE];
__device__ float g_cur[2][ROWS*DM];
__device__ __nv_bfloat16 g_cih[(size_t)ROWS2*KP];
__device__ __nv_bfloat16 g_cil[(size_t)ROWS2*KP];
__device__ __nv_bfloat16 g_temh[ROWS*DT];
__device__ __nv_bfloat16 g_teml[ROWS*DT];
__device__ __nv_bfloat16 g_wTh[3*4*256*KP];
__device__ __nv_bfloat16 g_wTl[3*4*256*KP];
__device__ float g_w32T[3*4*256*32];               // fp32 W rows 256..287, [z][hl][d][k]
__device__ __nv_bfloat16 g_qh[(size_t)ROWS2*DM];
__device__ __nv_bfloat16 g_ql[(size_t)ROWS2*DM];
__device__ __nv_bfloat16 g_kh[(size_t)ROWS2*DM];
__device__ __nv_bfloat16 g_kl[(size_t)ROWS2*DM];
__device__ float g_v[ROWS2*DM];
__device__ __nv_bfloat16 g_vTh[(size_t)N_SEQ*DM*LEN];
__device__ __nv_bfloat16 g_vTl[(size_t)N_SEQ*DM*LEN];
__device__ __nv_bfloat16 g_ph[(size_t)N_SEQ*LL2*LEN];
__device__ __nv_bfloat16 g_pl[(size_t)N_SEQ*LL2*LEN];
__device__ float g_pd[N_SEQ*LL2];
__device__ float g_sv[N_SEQ*DM];

// ---------------- helpers -----------------------------------------------------
__device__ __forceinline__ uint32_t smem_u32(const void* p) {
    uint32_t a;
    asm("{ .reg .u64 t; cvta.to.shared.u64 t, %1; cvt.u32.u64 %0, t; }" : "=r"(a) : "l"(p));
    return a;
}
#define LDSM4(r0, r1, r2, r3, addr) \
    asm volatile("ldmatrix.sync.aligned.m8n8.x4.shared.b16 {%0,%1,%2,%3}, [%4];" \
        : "=r"(r0), "=r"(r1), "=r"(r2), "=r"(r3) : "r"(addr))
#define MMA16816(c, a, b0, b1) \
    asm volatile("mma.sync.aligned.m16n8k16.row.col.f32.bf16.bf16.f32 " \
        "{%0,%1,%2,%3},{%4,%5,%6,%7},{%8,%9},{%0,%1,%2,%3};" \
        : "+f"((c)[0]), "+f"((c)[1]), "+f"((c)[2]), "+f"((c)[3]) \
        : "r"((a)[0]), "r"((a)[1]), "r"((a)[2]), "r"((a)[3]), "r"(b0), "r"(b1))
#define CPASYNC16(dst, src) \
    asm volatile("cp.async.ca.shared.global [%0], [%1], 16;" :: "r"(dst), "l"(src))
#define CPCOMMIT() asm volatile("cp.async.commit_group;" ::: "memory")
#define CPWAIT0()  asm volatile("cp.async.wait_group 0;" ::: "memory")
#define CPWAIT1()  asm volatile("cp.async.wait_group 1;" ::: "memory")

__device__ __forceinline__ void split_store(__nv_bfloat16* ph, __nv_bfloat16* pl,
                                            size_t idx, float v) {
    __nv_bfloat16 hi = __float2bfloat16(v);
    ph[idx] = hi;
    pl[idx] = __float2bfloat16(v - __bfloat162float(hi));
}

// ---------------- fused 3-term mma core ---------------------------------------
__device__ __forceinline__ void mma_core3(
    const __nv_bfloat16* Ah, const __nv_bfloat16* Al,
    const __nv_bfloat16* Bh, const __nv_bfloat16* Bl,
    int lda, int ldb, int nkt, uint32_t sbase, float acc[4][4][4])
{
    int tid = threadIdx.x;
    int w = tid >> 5, lane = tid & 31;
    int wm = (w & 1) << 6;
    int wn = (w >> 1) << 5;
    int lr = tid >> 1;
    int c2 = (tid & 1) << 1;

    const char* pAh = (const char*)(Ah + (size_t)lr * lda) + c2 * 16;
    const char* pAl = (const char*)(Al + (size_t)lr * lda) + c2 * 16;
    const char* pBh = (const char*)(Bh + (size_t)lr * ldb) + c2 * 16;
    const char* pBl = (const char*)(Bl + (size_t)lr * ldb) + c2 * 16;
    uint32_t sdst = sbase + lr * 80 + c2 * 16;

    {
        CPASYNC16(sdst,              pAh);       CPASYNC16(sdst + 16,              pAh + 16);
        CPASYNC16(sdst + TILE_B,     pAl);       CPASYNC16(sdst + TILE_B + 16,     pAl + 16);
        CPASYNC16(sdst + 2*TILE_B,   pBh);       CPASYNC16(sdst + 2*TILE_B + 16,   pBh + 16);
        CPASYNC16(sdst + 3*TILE_B,   pBl);       CPASYNC16(sdst + 3*TILE_B + 16,   pBl + 16);
        CPCOMMIT();
    }

    int buf = 0;
    for (int kt = 0; kt < nkt; kt++) {
        bool more = (kt + 1 < nkt);
        if (more) {
            int off = (kt + 1) * 64;
            uint32_t d = sdst + (buf ^ 1) * (4 * TILE_B);
            CPASYNC16(d,              pAh + off);       CPASYNC16(d + 16,              pAh + off + 16);
            CPASYNC16(d + TILE_B,     pAl + off);       CPASYNC16(d + TILE_B + 16,     pAl + off + 16);
            CPASYNC16(d + 2*TILE_B,   pBh + off);       CPASYNC16(d + 2*TILE_B + 16,   pBh + off + 16);
            CPASYNC16(d + 3*TILE_B,   pBl + off);       CPASYNC16(d + 3*TILE_B + 16,   pBl + off + 16);
            CPCOMMIT();
            CPWAIT1();
        } else {
            CPWAIT0();
        }
        __syncthreads();

        uint32_t bAh = sbase + buf * (4 * TILE_B);
        uint32_t bAl = bAh + TILE_B;
        uint32_t bBh = bAh + 2 * TILE_B;
        uint32_t bBl = bAh + 3 * TILE_B;
#pragma unroll
        for (int ks = 0; ks < 2; ks++) {
            uint32_t arow = (uint32_t)((lane & 15)) * 80 + (uint32_t)(ks * 2 + ((lane >> 4) & 1)) * 16;
            uint32_t brow = (uint32_t)((lane & 7) + ((lane >> 4) & 1) * 8) * 80
                          + (uint32_t)(ks * 2 + ((lane >> 3) & 1)) * 16;
            uint32_t bh[2][4], bl[2][4];
#pragma unroll
            for (int p = 0; p < 2; p++) {
                uint32_t ad = (uint32_t)(wn + p * 16) * 80 + brow;
                LDSM4(bh[p][0], bh[p][1], bh[p][2], bh[p][3], bBh + ad);
                LDSM4(bl[p][0], bl[p][1], bl[p][2], bl[p][3], bBl + ad);
            }
            uint32_t a[4][4];
#pragma unroll
            for (int mf = 0; mf < 4; mf++) {
                uint32_t ad = (uint32_t)(wm + mf * 16) * 80 + arow;
                LDSM4(a[mf][0], a[mf][1], a[mf][2], a[mf][3], bAh + ad);
            }
#pragma unroll
            for (int mf = 0; mf < 4; mf++)
#pragma unroll
                for (int nf = 0; nf < 4; nf++) {
                    MMA16816(acc[mf][nf], a[mf], bh[nf >> 1][(nf & 1) * 2], bh[nf >> 1][(nf & 1) * 2 + 1]);
                    MMA16816(acc[mf][nf], a[mf], bl[nf >> 1][(nf & 1) * 2], bl[nf >> 1][(nf & 1) * 2 + 1]);
                }
#pragma unroll
            for (int mf = 0; mf < 4; mf++) {
                uint32_t ad = (uint32_t)(wm + mf * 16) * 80 + arow;
                LDSM4(a[mf][0], a[mf][1], a[mf][2], a[mf][3], bAl + ad);
            }
#pragma unroll
            for (int mf = 0; mf < 4; mf++)
#pragma unroll
                for (int nf = 0; nf < 4; nf++)
                    MMA16816(acc[mf][nf], a[mf], bh[nf >> 1][(nf & 1) * 2], bh[nf >> 1][(nf & 1) * 2 + 1]);
        }
        __syncthreads();
        buf ^= 1;
    }
}

// ---------------- QKV epilogue -------------------------------------------------
__device__ __forceinline__ void qkv_epilogue(float acc[4][4][4], int z, int baseRow,
                                             int n0, const float* bias) {
    int w = threadIdx.x >> 5, lane = threadIdx.x & 31;
    int wm = (w & 1) << 6, wn = (w >> 1) << 5;
    int r0 = lane >> 2, c0 = (lane & 3) << 1;
#pragma unroll
    for (int mf = 0; mf < 4; mf++)
#pragma unroll
        for (int nf = 0; nf < 4; nf++) {
            int row = baseRow + wm + mf * 16 + r0;
            int col = n0 + wn + nf * 8 + c0;
#pragma unroll
            for (int q = 0; q < 4; q++) {
                size_t idx = (size_t)(row + (q >> 1) * 8) * DM + col + (q & 1);
                float val = acc[mf][nf][q] + bias[col + (q & 1)];
                if (z == 2) g_v[idx] = val;
                else if (z == 0) split_store(g_qh, g_ql, idx, val);
                else             split_store(g_kh, g_kl, idx, val);
            }
        }
}

// ---------------- fused prep ---------------------------------------------------
#define PR0 ((size_t)ROWS*KE)
#define PR1 (PR0 + (size_t)ROWS*16)
#define PR2 (PR1 + (size_t)2*ROWS*DM)
#define PR3 (PR2 + (size_t)3*4*256*KP)
#define PR4 (PR3 + (size_t)3*4*256*32)
__global__ void k_prep(const int* __restrict__ subj, const int* __restrict__ obj,
                       const int* __restrict__ rel, const float* __restrict__ ent,
                       const float* __restrict__ relw, const float* __restrict__ time,
                       const float* __restrict__ qw, const float* __restrict__ kw,
                       const float* __restrict__ vw) {
    size_t i = (size_t)blockIdx.x * 256 + threadIdx.x;
    if (i < PR0) {
        int row = (int)(i / KE);
        int c   = (int)(i - (size_t)row * KE);
        float v;
        if (c < 128)      v = ent[subj[row] * 128 + c];
        else if (c < 256) v = ent[obj[row] * 128 + (c - 128)];
        else              v = relw[rel[row] * 128 + (c - 256)];
        g_emb[i] = v;
    } else if (i < PR1) {
        size_t j = i - PR0;
        int row = (int)(j >> 4);
        int f   = (int)(j & 15);
        float t = time[row];
        float div = expf((float)(2 * f) * -0.28782313662425576f);
        float arg = t * div;
        float np  = (t > 0.f) ? 1.f : 0.f;
        float s = sinf(arg) * np;
        float c = cosf(arg) * np;
        int n = row >> 7, l = row & 127;
        size_t rT = ((size_t)n * LL2 + l) * KP + 256 + 2 * f;
        size_t rB = rT + (size_t)128 * KP;
        split_store(g_cih, g_cil, rT, s);
        split_store(g_cih, g_cil, rT + 1, c);
        split_store(g_cih, g_cil, rB, s);
        split_store(g_cih, g_cil, rB + 1, c);
        split_store(g_temh, g_teml, (size_t)row * DT + 2 * f, s);
        split_store(g_temh, g_teml, (size_t)row * DT + 2 * f + 1, c);
    } else if (i < PR2) {
        ((float*)g_cur)[i - PR1] = 0.f;
    } else if (i < PR3) {
        size_t j = i - PR2;
        int k  = (int)(j % KP);
        int n  = (int)((j / KP) & 255);
        int hl = (int)((j / (KP * 256)) & 3);
        int z  = (int)(j / ((size_t)KP * 256 * 4));
        const float* W = (z == 0) ? qw : (z == 1) ? kw : vw;
        float v = W[(hl * DIN + k) * 256 + n];
        split_store(g_wTh, g_wTl, j, v);
    } else if (i < PR4) {
        size_t j = i - PR3;
        int k  = (int)(j & 31);
        int d  = (int)((j >> 5) & 255);
        int hl = (int)((j >> 13) & 3);
        int z  = (int)(j >> 15);
        const float* W = (z == 0) ? qw : (z == 1) ? kw : vw;
        g_w32T[j] = W[(hl * DIN + 256 + k) * 256 + d];
    }
}

// ---------------- QKV mma, mode-dispatched -------------------------------------
// mode 1: top rows, all z (grid 6, N_SEQ)
// mode 2: top rows, z in {1,2}   (grid 4, N_SEQ)
// mode 3: bottom rows, z=2 only  (grid 2, N_SEQ)
__global__ __launch_bounds__(256, 2) void k_qkv_mma(const float* __restrict__ qb,
                                                    const float* __restrict__ kb,
                                                    const float* __restrict__ vb,
                                                    int hl, int mode) {
    extern __shared__ __nv_bfloat16 smem_dyn[];
    uint32_t sbase = smem_u32(smem_dyn);
    int z, n0, m0;
    if (mode == 1)      { z = blockIdx.x >> 1;       n0 = (blockIdx.x & 1) << 7; m0 = blockIdx.y << 8; }
    else if (mode == 2) { z = 1 + (blockIdx.x >> 1); n0 = (blockIdx.x & 1) << 7; m0 = blockIdx.y << 8; }
    else                { z = 2;                     n0 = blockIdx.x << 7;       m0 = (blockIdx.y << 8) + 128; }

    float acc[4][4][4] = {};
    mma_core3(g_cih + (size_t)m0 * KP, g_cil + (size_t)m0 * KP,
              g_wTh + ((size_t)(z * 4 + hl) * 256 + n0) * KP,
              g_wTl + ((size_t)(z * 4 + hl) * 256 + n0) * KP,
              KP, KP, 9, sbase, acc);
    qkv_epilogue(acc, z, m0, n0, ((z == 0) ? qb : (z == 1) ? kb : vb) + hl * 256);
}

// ---------------- QKV bottom at l=0: scalar FFMA, K=32 (tem only) --------------
// grid (3, N_SEQ), block 256: z = blockIdx.x, thread = output column d.
__global__ __launch_bounds__(256) void k_bot(const float* __restrict__ qb,
                                             const float* __restrict__ kb,
                                             const float* __restrict__ vb, int hl) {
    __shared__ float st[128 * 32];
    int z = blockIdx.x, n = blockIdx.y;
    int d = threadIdx.x;

    // stage tem rows (fp32) in smem
    for (int e = threadIdx.x; e < 128 * 32; e += 256) {
        size_t g = (size_t)(n * LEN) * DT + e;
        st[e] = __bfloat162float(g_temh[g]) + __bfloat162float(g_teml[g]);
    }
    __syncthreads();

    // W column strip in registers
    float wr[32];
    const float4* wp = (const float4*)(g_w32T + ((size_t)(z * 4 + hl) * 256 + d) * 32);
#pragma unroll
    for (int k4 = 0; k4 < 8; k4++) {
        float4 w4 = wp[k4];
        wr[k4 * 4] = w4.x; wr[k4 * 4 + 1] = w4.y; wr[k4 * 4 + 2] = w4.z; wr[k4 * 4 + 3] = w4.w;
    }
    float bias = ((z == 0) ? qb : (z == 1) ? kb : vb)[hl * 256 + d];

    for (int r = 0; r < 128; r++) {
        const float* tr = st + r * 32;
        float acc = bias;
#pragma unroll
        for (int k = 0; k < 32; k++) acc += wr[k] * tr[k];
        size_t idx = ((size_t)(n * LL2 + 128 + r)) * DM + d;
        if (z == 2) g_v[idx] = acc;
        else if (z == 0) split_store(g_qh, g_ql, idx, acc);
        else             split_store(g_kh, g_kl, idx, acc);
    }
}

// ---------------- fused V transpose + sv ---------------------------------------
// grid (9, N_SEQ): x<8 vt d-slices; x==8 sv column sums.
__global__ __launch_bounds__(256) void k_vtsv() {
    __shared__ float tile[128][33];
    int n = blockIdx.y, xx = blockIdx.x;
    if (xx < 8) {
        int d0 = xx << 5;
        for (int el = threadIdx.x; el < 4096; el += 256) {
            int key = el >> 5, d = el & 31;
            tile[key][d] = g_v[((size_t)n * LL2 + key) * DM + d0 + d];
        }
        __syncthreads();
        for (int el = threadIdx.x; el < 4096; el += 256) {
            int d = el >> 7, key = el & 127;
            size_t o = (size_t)n * DM * LEN + (size_t)(d0 + d) * LEN + key;
            split_store(g_vTh, g_vTl, o, tile[key][d]);
        }
    } else {
        int d = threadIdx.x;
        const float* vp = g_v + (n * LL2 + LEN) * DM + d;
        float s = 0.f;
#pragma unroll 8
        for (int j = 0; j < LEN; j++) s += vp[j * DM];
        g_sv[n * DM + d] = s;
    }
}

// ---------------- fused scores mma + masked softmax ----------------------------
__global__ __launch_bounds__(256, 2) void k_scores_sm(const float* __restrict__ time) {
    extern __shared__ __nv_bfloat16 smem_dyn[];
    uint32_t sbase = smem_u32(smem_dyn);
    int n  = blockIdx.y;
    int m0 = blockIdx.x << 7;

    float acc[4][4][4] = {};
    mma_core3(g_qh + ((size_t)n * LL2 + m0) * DM, g_ql + ((size_t)n * LL2 + m0) * DM,
              g_kh + (size_t)n * LL2 * DM, g_kl + (size_t)n * LL2 * DM,
              DM, DM, 8, sbase, acc);

    float* P = (float*)smem_dyn;
    const int LDP = 132;
    float* stt = P + 128 * LDP;
    int w = threadIdx.x >> 5, lane = threadIdx.x & 31;
    int wm = (w & 1) << 6, wn = (w >> 1) << 5;
    int r0 = lane >> 2, c0 = (lane & 3) << 1;
#pragma unroll
    for (int mf = 0; mf < 4; mf++)
#pragma unroll
        for (int nf = 0; nf < 4; nf++) {
            int row = wm + mf * 16 + r0;
            int col = wn + nf * 8 + c0;
            P[row * LDP + col]           = acc[mf][nf][0] * 0.0625f;
            P[row * LDP + col + 1]       = acc[mf][nf][1] * 0.0625f;
            P[(row + 8) * LDP + col]     = acc[mf][nf][2] * 0.0625f;
            P[(row + 8) * LDP + col + 1] = acc[mf][nf][3] * 0.0625f;
        }
    if (threadIdx.x < 128) stt[threadIdx.x] = time[n * LEN + threadIdx.x];
    __syncthreads();

    bool bottom = (m0 == LEN);
    for (int rr = 0; rr < 16; rr++) {
        int r = w * 16 + rr;
        int rowId = n * LL2 + m0 + r;
        __nv_bfloat16* oh = g_ph + (size_t)rowId * LEN;
        __nv_bfloat16* ol = g_pl + (size_t)rowId * LEN;

        float vals[4];
        float mx = -1e30f;
#pragma unroll
        for (int c = 0; c < 4; c++) {
            int j = lane + c * 32;
            float s = P[r * LDP + j];
            bool masked = (j >= r) || (stt[j] == 0.f);
            s = masked ? -1e9f : s;
            vals[c] = s;
            mx = fmaxf(mx, s);
        }
        float d = 0.f;
        if (bottom) {
            size_t base = (size_t)(n * LL2 + LEN + r) * DM / 2;
            const __nv_bfloat162* qh2 = (const __nv_bfloat162*)g_qh + base;
            const __nv_bfloat162* ql2 = (const __nv_bfloat162*)g_ql + base;
            const __nv_bfloat162* kh2 = (const __nv_bfloat162*)g_kh + base;
            const __nv_bfloat162* kl2 = (const __nv_bfloat162*)g_kl + base;
#pragma unroll
            for (int c = 0; c < 4; c++) {
                int idx = lane * 4 + c;
                __nv_bfloat162 a = qh2[idx], b = ql2[idx], e = kh2[idx], f = kl2[idx];
                float qx = __bfloat162float(a.x) + __bfloat162float(b.x);
                float qy = __bfloat162float(a.y) + __bfloat162float(b.y);
                float kx = __bfloat162float(e.x) + __bfloat162float(f.x);
                float ky = __bfloat162float(e.y) + __bfloat162float(f.y);
                d += qx * kx + qy * ky;
            }
#pragma unroll
            for (int off = 16; off; off >>= 1) d += __shfl_xor_sync(0xffffffffu, d, off);
            d *= 0.0625f;
        }
#pragma unroll
        for (int off = 16; off; off >>= 1) mx = fmaxf(mx, __shfl_xor_sync(0xffffffffu, mx, off));

        if (!bottom && mx < -5e8f) {
            __nv_bfloat16 u = __float2bfloat16(1.0f / 256.0f);
#pragma unroll
            for (int c = 0; c < 4; c++) { oh[lane + c * 32] = u; ol[lane + c * 32] = __float2bfloat16(0.f); }
            if (lane == 0) g_pd[rowId] = 1.0f / 256.0f;
            continue;
        }
        if (bottom) mx = fmaxf(mx, d);
        float sum = 0.f;
#pragma unroll
        for (int c = 0; c < 4; c++) { vals[c] = expf(vals[c] - mx); sum += vals[c]; }
#pragma unroll
        for (int off = 16; off; off >>= 1) sum += __shfl_xor_sync(0xffffffffu, sum, off);
        float ed = bottom ? expf(d - mx) : 0.f;
        float inv = 1.f / (sum + ed);
#pragma unroll
        for (int c = 0; c < 4; c++) {
            float p = vals[c] * inv;
            __nv_bfloat16 hi = __float2bfloat16(p);
            oh[lane + c * 32] = hi;
            ol[lane + c * 32] = __float2bfloat16(p - __bfloat162float(hi));
        }
        if (lane == 0) g_pd[rowId] = ed * inv;
    }
}

// ---------------- PV mma + fused residual update / ci write --------------------
// Top rows: ci top = O. Bottom rows (only launched at l=0): cur += tanh(O*np),
// ci bottom = new cur.
__global__ __launch_bounds__(256, 2) void k_pv_mma(const float* __restrict__ time, int h) {
    extern __shared__ __nv_bfloat16 smem_dyn[];
    uint32_t sbase = smem_u32(smem_dyn);
    int n  = blockIdx.z;
    int m0 = blockIdx.y << 7;
    int n0 = blockIdx.x << 7;

    float acc[4][4][4] = {};
    mma_core3(g_ph + ((size_t)n * LL2 + m0) * LEN, g_pl + ((size_t)n * LL2 + m0) * LEN,
              g_vTh + ((size_t)n * DM + n0) * LEN, g_vTl + ((size_t)n * DM + n0) * LEN,
              LEN, LEN, 4, sbase, acc);

    int w = threadIdx.x >> 5, lane = threadIdx.x & 31;
    int wm = (w & 1) << 6, wn = (w >> 1) << 5;
    int r0 = lane >> 2, c0 = (lane & 3) << 1;
    const float* V = g_v + (size_t)n * LL2 * DM;
#pragma unroll
    for (int mf = 0; mf < 4; mf++)
#pragma unroll
        for (int nf = 0; nf < 4; nf++) {
            int row = m0 + wm + mf * 16 + r0;
            int col = n0 + wn + nf * 8 + c0;
#pragma unroll
            for (int q = 0; q < 4; q++) {
                int r = row + (q >> 1) * 8;
                int c = col + (q & 1);
                float pd = g_pd[n * LL2 + r];
                float extra = (r < LEN) ? g_sv[n * DM + c] : V[(size_t)r * DM + c];
                float o = acc[mf][nf][q] + pd * extra;
                if (r < LEN) {
                    split_store(g_cih, g_cil, ((size_t)n * LL2 + r) * KP + c, o);
                } else {
                    int l = r - LEN;
                    float np = (time[n * LEN + l] > 0.f) ? 1.f : 0.f;
                    size_t ci = ((size_t)n * LEN + l) * DM + c;
                    float nc = g_cur[h][ci] + tanhf(o * np);
                    g_cur[h][ci] = nc;
                    split_store(g_cih, g_cil, ((size_t)n * LL2 + r) * KP + c, nc);
                }
            }
        }
}

// ---------------- last-row attention (l=1): cur[h][:,127] only -----------------
__global__ __launch_bounds__(256) void k_last(const float* __restrict__ time,
                                              const float* __restrict__ qb,
                                              const float* __restrict__ kb,
                                              const float* __restrict__ vb,
                                              int h, int hl) {
    __shared__ float ci[KP];
    __shared__ float qv[256], kv2[256], vv2[256];
    __shared__ float sp[128];
    __shared__ float spd[1];
    int n = blockIdx.x, t = threadIdx.x;
    int w = t >> 5, lane = t & 31;

    size_t rb = ((size_t)n * LL2 + 255) * KP;
    for (int kk = t; kk < KP; kk += 256)
        ci[kk] = __bfloat162float(g_cih[rb + kk]) + __bfloat162float(g_cil[rb + kk]);
    __syncthreads();

    for (int idx = w; idx < 768; idx += 8) {
        int z = idx >> 8, d = idx & 255;
        const __nv_bfloat16* wh = g_wTh + ((size_t)(z * 4 + hl) * 256 + d) * KP;
        const __nv_bfloat16* wl = g_wTl + ((size_t)(z * 4 + hl) * 256 + d) * KP;
        float s = 0.f;
        for (int kk = lane; kk < KP; kk += 32)
            s += ci[kk] * (__bfloat162float(wh[kk]) + __bfloat162float(wl[kk]));
#pragma unroll
        for (int o = 16; o; o >>= 1) s += __shfl_xor_sync(0xffffffffu, s, o);
        if (lane == 0) {
            if (z == 0)      qv[d]  = s + qb[hl * 256 + d];
            else if (z == 1) kv2[d] = s + kb[hl * 256 + d];
            else             vv2[d] = s + vb[hl * 256 + d];
        }
    }
    __syncthreads();

    const float* tt = time + n * LEN;
    for (int j = w; j < 128; j += 8) {
        const __nv_bfloat16* kh = g_kh + ((size_t)n * LL2 + j) * DM;
        const __nv_bfloat16* kl = g_kl + ((size_t)n * LL2 + j) * DM;
        float s = 0.f;
        for (int d = lane; d < 256; d += 32)
            s += qv[d] * (__bfloat162float(kh[d]) + __bfloat162float(kl[d]));
#pragma unroll
        for (int o = 16; o; o >>= 1) s += __shfl_xor_sync(0xffffffffu, s, o);
        if (lane == 0) {
            bool masked = (j >= 127) || (tt[j] == 0.f);
            sp[j] = masked ? -1e9f : s * 0.0625f;
        }
    }
    __syncthreads();

    if (w == 0) {
        float dd = 0.f;
        for (int d = lane; d < 256; d += 32) dd += qv[d] * kv2[d];
#pragma unroll
        for (int o = 16; o; o >>= 1) dd += __shfl_xor_sync(0xffffffffu, dd, o);
        dd *= 0.0625f;

        float vals[4];
        float mx = dd;
#pragma unroll
        for (int c = 0; c < 4; c++) { vals[c] = sp[lane + c * 32]; mx = fmaxf(mx, vals[c]); }
#pragma unroll
        for (int o = 16; o; o >>= 1) mx = fmaxf(mx, __shfl_xor_sync(0xffffffffu, mx, o));
        float sum = 0.f;
#pragma unroll
        for (int c = 0; c < 4; c++) { vals[c] = expf(vals[c] - mx); sum += vals[c]; }
#pragma unroll
        for (int o = 16; o; o >>= 1) sum += __shfl_xor_sync(0xffffffffu, sum, o);
        float ed = expf(dd - mx);
        float inv = 1.f / (sum + ed);
#pragma unroll
        for (int c = 0; c < 4; c++) sp[lane + c * 32] = vals[c] * inv;
        if (lane == 0) spd[0] = ed * inv;
    }
    __syncthreads();

    float o = 0.f;
    const float* V = g_v + (size_t)n * LL2 * DM + t;
    for (int j = 0; j < 128; j++) o += sp[j] * V[(size_t)j * DM];
    o += spd[0] * vv2[t];
    float np = (tt[127] > 0.f) ? 1.f : 0.f;
    g_cur[h][((size_t)n * LEN + 127) * DM + t] += tanhf(o * np);
}

// ---------------- FFMA GEMM for input projection (writes ci) -------------------
__device__ __forceinline__ void gemm_compute(const float (*As)[140], const float (*Bs)[128],
                                             float acc[8][8], int tx, int ty) {
#pragma unroll
    for (int k = 0; k < 8; k++) {
        float a[8], b[8];
        *(float4*)(a)     = *(const float4*)&As[k][ty * 4];
        *(float4*)(a + 4) = *(const float4*)&As[k][64 + ty * 4];
        *(float4*)(b)     = *(const float4*)&Bs[k][tx * 4];
        *(float4*)(b + 4) = *(const float4*)&Bs[k][64 + tx * 4];
#pragma unroll
        for (int i = 0; i < 8; i++)
#pragma unroll
            for (int j = 0; j < 8; j++)
                acc[i][j] += a[i] * b[j];
    }
}

__global__ __launch_bounds__(256) void k_gemm_x(const float* __restrict__ W,
                                                const float* __restrict__ bias) {
    __shared__ float As[2][8][140];
    __shared__ float Bs[2][8][128];
    float acc[8][8] = {};
    int m0 = blockIdx.y << 7, n0 = blockIdx.x << 7;
    int tid = threadIdx.x;
    int tx = tid & 15, ty = tid >> 4;
    int ar = tid >> 1, kg = (tid & 1) << 2;
    int br = tid >> 5, bc = (tid & 31) << 2;

    float4 a = *(const float4*)(g_emb + (m0 + ar) * KE + kg);
    float4 b = *(const float4*)(W + br * DM + n0 + bc);
    As[0][kg][ar] = a.x; As[0][kg + 1][ar] = a.y; As[0][kg + 2][ar] = a.z; As[0][kg + 3][ar] = a.w;
    *(float4*)&Bs[0][br][bc] = b;
    __syncthreads();

    int buf = 0;
    for (int k0 = 8; k0 < KE; k0 += 8) {
        float4 an = *(const float4*)(g_emb + (m0 + ar) * KE + k0 + kg);
        float4 bn = *(const float4*)(W + (k0 + br) * DM + n0 + bc);
        gemm_compute(As[buf], Bs[buf], acc, tx, ty);
        int nb = buf ^ 1;
        As[nb][kg][ar] = an.x; As[nb][kg + 1][ar] = an.y; As[nb][kg + 2][ar] = an.z; As[nb][kg + 3][ar] = an.w;
        *(float4*)&Bs[nb][br][bc] = bn;
        __syncthreads();
        buf = nb;
    }
    gemm_compute(As[buf], Bs[buf], acc, tx, ty);

#pragma unroll
    for (int i = 0; i < 8; i++) {
        int r = m0 + ((i < 4) ? (ty << 2) + i : 64 + (ty << 2) + i - 4);
        int n = r >> 7, l = r & 127;
#pragma unroll
        for (int j = 0; j < 8; j++) {
            int c = n0 + ((j < 4) ? (tx << 2) + j : 64 + (tx << 2) + j - 4);
            split_store(g_cih, g_cil, ((size_t)n * LL2 + l) * KP + c, acc[i][j] + bias[c]);
        }
    }
}

// ---------------- final MLP head -----------------------------------------------
__global__ __launch_bounds__(256) void k_head(const float* __restrict__ w1,
                                              const float* __restrict__ b1,
                                              const float* __restrict__ w2,
                                              const float* __restrict__ b2,
                                              float* __restrict__ out) {
    int n = blockIdx.x;
    int t = threadIdx.x;
    __shared__ float sl[512];
    __shared__ float sh[256];
    sl[t]       = g_cur[0][(n * LEN + LEN - 1) * DM + t];
    sl[256 + t] = g_cur[1][(n * LEN + LEN - 1) * DM + t];
    __syncthreads();
    float acc = b1[t];
    for (int k = 0; k < 512; k++) acc += sl[k] * w1[k * DM + t];
    float x = acc;
    float g = 0.5f * x * (1.f + erff(x * 0.7071067811865476f));
    sh[t] = g * w2[t];
    __syncthreads();
    for (int s = 128; s > 0; s >>= 1) {
        if (t < s) sh[t] += sh[t + s];
        __syncthreads();
    }
    if (t == 0) out[n] = sh[0] + b2[0];
}

// ---------------- launch --------------------------------------------------------
extern "C" void kernel_launch(void* const* d_in, const int* in_sizes, int n_in,
                              void* d_out, int out_size) {
    const int*   subj = (const int*)d_in[0];
    const int*   obj  = (const int*)d_in[1];
    const int*   rel  = (const int*)d_in[2];
    const float* time = (const float*)d_in[3];
    const float* ent  = (const float*)d_in[4];
    const float* relw = (const float*)d_in[5];
    const float* in_w = (const float*)d_in[6];
    const float* in_b = (const float*)d_in[7];
    const float* q_w  = (const float*)d_in[8];
    const float* q_b  = (const float*)d_in[9];
    const float* k_w  = (const float*)d_in[10];
    const float* k_b  = (const float*)d_in[11];
    const float* v_w  = (const float*)d_in[12];
    const float* v_b  = (const float*)d_in[13];
    const float* w1   = (const float*)d_in[14];
    const float* b1   = (const float*)d_in[15];
    const float* w2   = (const float*)d_in[16];
    const float* b2   = (const float*)d_in[17];
    float* out = (float*)d_out;

    cudaFuncSetAttribute(k_qkv_mma,   cudaFuncAttributeMaxDynamicSharedMemorySize, SMEM_MMA);
    cudaFuncSetAttribute(k_scores_sm, cudaFuncAttributeMaxDynamicSharedMemorySize, SMEM_MMA);
    cudaFuncSetAttribute(k_pv_mma,    cudaFuncAttributeMaxDynamicSharedMemorySize, SMEM_MMA);

    k_prep<<<(unsigned)((PR4 + 255) / 256), 256>>>(subj, obj, rel, ent, relw, time, q_w, k_w, v_w);
    k_gemm_x<<<dim3(DM / 128, ROWS / 128), 256>>>(in_w, in_b);

    for (int h = 0; h < 2; h++) {
        for (int l = 0; l < 2; l++) {
            int hl = h * 2 + l;
            if (l == 0) {
                k_qkv_mma<<<dim3(6, N_SEQ), 256, SMEM_MMA>>>(q_b, k_b, v_b, hl, 1);
                k_bot<<<dim3(3, N_SEQ), 256>>>(q_b, k_b, v_b, hl);
                k_vtsv<<<dim3(9, N_SEQ), 256>>>();
                k_scores_sm<<<dim3(2, N_SEQ), 256, SMEM_MMA>>>(time);
                k_pv_mma<<<dim3(2, 2, N_SEQ), 256, SMEM_MMA>>>(time, h);
            } else if (h == 0) {
                k_qkv_mma<<<dim3(6, N_SEQ), 256, SMEM_MMA>>>(q_b, k_b, v_b, hl, 1);
                k_qkv_mma<<<dim3(2, N_SEQ), 256, SMEM_MMA>>>(q_b, k_b, v_b, hl, 3);
                k_vtsv<<<dim3(9, N_SEQ), 256>>>();
                k_scores_sm<<<dim3(1, N_SEQ), 256, SMEM_MMA>>>(time);
                k_pv_mma<<<dim3(2, 1, N_SEQ), 256, SMEM_MMA>>>(time, h);
                k_last<<<N_SEQ, 256>>>(time, q_b, k_b, v_b, h, hl);
            } else {
                k_qkv_mma<<<dim3(4, N_SEQ), 256, SMEM_MMA>>>(q_b, k_b, v_b, hl, 2);
                k_last<<<N_SEQ, 256>>>(time, q_b, k_b, v_b, h, hl);
            }
        }
    }
    k_head<<<N_SEQ, 256>>>(w1, b1, w2, b2, out);
}